// round 6
// baseline (speedup 1.0000x reference)
#include <cuda_runtime.h>
#include <cuda_bf16.h>
#include <cstdint>
#include <cstddef>

#define BQ 2
#define QL 1024
#define ML 1024
#define KL 2048
#define DM 1024
#define NH 16
#define DH 64

// ---------------- scratch (device globals: allocation-free) ----------------
__device__ float g_w[(size_t)4096 * 3072];          // cat @ W_qkv  [B*K, 3D]
__device__ float g_rp[(size_t)4096 * 1024];         // r @ W_r      [B*K, D]
__device__ float g_score[(size_t)32 * 1024 * 2048]; // AC [B*H, Q, K]
__device__ float g_bd[(size_t)32 * 1024 * 2048];    // BD (pre-shifted) [B*H, Q, K]
__device__ float g_attn[(size_t)2048 * 1024];       // [B*Q, D]

// dense GEMM bf16 hi/lo splits
__device__ __nv_bfloat16 g_ah[(size_t)4096 * 1024], g_al[(size_t)4096 * 1024];
__device__ __nv_bfloat16 g_rh[(size_t)4096 * 1024], g_rl[(size_t)4096 * 1024];
__device__ __nv_bfloat16 g_oh[(size_t)2048 * 1024], g_ol[(size_t)2048 * 1024];
__device__ __nv_bfloat16 g_wqh[(size_t)3072 * 1024], g_wql[(size_t)3072 * 1024];
__device__ __nv_bfloat16 g_wrh[(size_t)1024 * 1024], g_wrl[(size_t)1024 * 1024];
__device__ __nv_bfloat16 g_woh[(size_t)1024 * 1024], g_wol[(size_t)1024 * 1024];

// per-head attention operands (bf16 hi/lo)
__device__ __nv_bfloat16 g_quh[(size_t)32 * 1024 * 64], g_qul[(size_t)32 * 1024 * 64];
__device__ __nv_bfloat16 g_qvh[(size_t)32 * 1024 * 64], g_qvl[(size_t)32 * 1024 * 64];
__device__ __nv_bfloat16 g_khh[(size_t)32 * 2048 * 64], g_khl[(size_t)32 * 2048 * 64];
__device__ __nv_bfloat16 g_rrh[(size_t)32 * 2048 * 64], g_rrl[(size_t)32 * 2048 * 64];
__device__ __nv_bfloat16 g_vth[(size_t)32 * 64 * 2048], g_vtl[(size_t)32 * 64 * 2048];

// ======================= helpers ===========================================
__device__ __forceinline__ uint32_t smem_u32(const void* p) {
    uint32_t a;
    asm("{ .reg .u64 t; cvta.to.shared.u64 t, %1; cvt.u32.u64 %0, t; }"
        : "=r"(a) : "l"(p));
    return a;
}
__device__ __forceinline__ void split1(float x, __nv_bfloat16& h, __nv_bfloat16& l) {
    h = __float2bfloat16_rn(x);
    l = __float2bfloat16_rn(x - __bfloat162float(h));
}
__device__ __forceinline__ uint32_t pack2(__nv_bfloat16 a, __nv_bfloat16 b) {
    __nv_bfloat162 v = make_bfloat162(a, b);
    return *(uint32_t*)&v;
}
__device__ __forceinline__ void ldmx4(uint32_t a[4], uint32_t addr) {
    asm volatile("ldmatrix.sync.aligned.m8n8.x4.shared.b16 {%0,%1,%2,%3}, [%4];"
        : "=r"(a[0]), "=r"(a[1]), "=r"(a[2]), "=r"(a[3]) : "r"(addr));
}
__device__ __forceinline__ void ldmx2(uint32_t a[2], uint32_t addr) {
    asm volatile("ldmatrix.sync.aligned.m8n8.x2.shared.b16 {%0,%1}, [%2];"
        : "=r"(a[0]), "=r"(a[1]) : "r"(addr));
}
__device__ __forceinline__ void mma16816(float c[4], const uint32_t a[4], const uint32_t b[2]) {
    asm volatile("mma.sync.aligned.m16n8k16.row.col.f32.bf16.bf16.f32 "
        "{%0,%1,%2,%3}, {%4,%5,%6,%7}, {%8,%9}, {%0,%1,%2,%3};"
        : "+f"(c[0]), "+f"(c[1]), "+f"(c[2]), "+f"(c[3])
        : "r"(a[0]), "r"(a[1]), "r"(a[2]), "r"(a[3]), "r"(b[0]), "r"(b[1]));
}
#define CP16(dst, src) \
    asm volatile("cp.async.cg.shared.global [%0], [%1], 16;" :: "r"(dst), "l"(src) : "memory")
#define CP_COMMIT() asm volatile("cp.async.commit_group;" ::: "memory")
#define CP_WAIT(n)  asm volatile("cp.async.wait_group %0;" :: "n"(n) : "memory")

// ===================== prep: split kernels ==================================
__global__ __launch_bounds__(256)
void split_concat(const float* __restrict__ mem, const float* __restrict__ inp,
                  __nv_bfloat16* __restrict__ hi, __nv_bfloat16* __restrict__ lo)
{
    size_t idx = ((size_t)blockIdx.x * 256 + threadIdx.x) * 4;
    size_t row = idx >> 10;
    int col = (int)(idx & 1023);
    int b = (int)(row >> 11);
    int k = (int)(row & 2047);
    const float* src = (k < ML) ? mem + ((size_t)(b * ML + k) << 10)
                                : inp + ((size_t)(b * QL + (k - ML)) << 10);
    float4 v = *(const float4*)(src + col);
    __nv_bfloat16 h0, h1, h2, h3, l0, l1, l2, l3;
    split1(v.x, h0, l0); split1(v.y, h1, l1);
    split1(v.z, h2, l2); split1(v.w, h3, l3);
    __nv_bfloat162* H = (__nv_bfloat162*)(hi + idx);
    __nv_bfloat162* L = (__nv_bfloat162*)(lo + idx);
    H[0] = make_bfloat162(h0, h1); H[1] = make_bfloat162(h2, h3);
    L[0] = make_bfloat162(l0, l1); L[1] = make_bfloat162(l2, l3);
}

__global__ __launch_bounds__(256)
void split_plain(const float* __restrict__ src,
                 __nv_bfloat16* __restrict__ hi, __nv_bfloat16* __restrict__ lo)
{
    size_t idx = ((size_t)blockIdx.x * 256 + threadIdx.x) * 4;
    float4 v = *(const float4*)(src + idx);
    __nv_bfloat16 h0, h1, h2, h3, l0, l1, l2, l3;
    split1(v.x, h0, l0); split1(v.y, h1, l1);
    split1(v.z, h2, l2); split1(v.w, h3, l3);
    __nv_bfloat162* H = (__nv_bfloat162*)(hi + idx);
    __nv_bfloat162* L = (__nv_bfloat162*)(lo + idx);
    H[0] = make_bfloat162(h0, h1); H[1] = make_bfloat162(h2, h3);
    L[0] = make_bfloat162(l0, l1); L[1] = make_bfloat162(l2, l3);
}

__global__ __launch_bounds__(256)
void split_transpose(const float* __restrict__ in,
                     __nv_bfloat16* __restrict__ hi, __nv_bfloat16* __restrict__ lo, int N)
{
    __shared__ float s[32][33];
    const int nx = blockIdx.x * 32;
    const int ky = blockIdx.y * 32;
    const int tx = threadIdx.x & 31;
    const int ty = threadIdx.x >> 5;
#pragma unroll
    for (int r = 0; r < 32; r += 8)
        s[ty + r][tx] = in[(size_t)(ky + ty + r) * N + nx + tx];
    __syncthreads();
#pragma unroll
    for (int r = 0; r < 32; r += 8) {
        float x = s[tx][ty + r];
        __nv_bfloat16 h, l;
        split1(x, h, l);
        size_t o = (size_t)(nx + ty + r) * DM + ky + tx;
        hi[o] = h;
        lo[o] = l;
    }
}

// per-head operands: qu/qv (rows i), k/r (rows j), all [bh][row][64] K-major
__global__ __launch_bounds__(256)
void split_heads(const float* __restrict__ u, const float* __restrict__ v)
{
    size_t gid = (size_t)blockIdx.x * 256 + threadIdx.x;
    int d = (int)(gid & 15) * 4;
    int h = (int)(gid >> 4) & 15;
    int j = (int)(gid >> 8) & 2047;
    int b = (int)(gid >> 19);
    size_t wrow = (size_t)(b * KL + j);
    size_t orow = ((size_t)(b * NH + h) * KL + j) * DH + d;

    float4 kx = *(const float4*)(g_w + wrow * 3072 + 2 * DM + h * DH + d);
    float4 rx = *(const float4*)(g_rp + wrow * DM + h * DH + d);
    __nv_bfloat16 h0, l0, h1, l1, h2, l2, h3, l3;
    split1(kx.x, h0, l0); split1(kx.y, h1, l1); split1(kx.z, h2, l2); split1(kx.w, h3, l3);
    *(__nv_bfloat162*)(g_khh + orow)     = make_bfloat162(h0, h1);
    *(__nv_bfloat162*)(g_khh + orow + 2) = make_bfloat162(h2, h3);
    *(__nv_bfloat162*)(g_khl + orow)     = make_bfloat162(l0, l1);
    *(__nv_bfloat162*)(g_khl + orow + 2) = make_bfloat162(l2, l3);
    split1(rx.x, h0, l0); split1(rx.y, h1, l1); split1(rx.z, h2, l2); split1(rx.w, h3, l3);
    *(__nv_bfloat162*)(g_rrh + orow)     = make_bfloat162(h0, h1);
    *(__nv_bfloat162*)(g_rrh + orow + 2) = make_bfloat162(h2, h3);
    *(__nv_bfloat162*)(g_rrl + orow)     = make_bfloat162(l0, l1);
    *(__nv_bfloat162*)(g_rrl + orow + 2) = make_bfloat162(l2, l3);

    if (j >= ML) {
        int i = j - ML;
        size_t qrow = ((size_t)(b * NH + h) * QL + i) * DH + d;
        float4 qx = *(const float4*)(g_w + wrow * 3072 + h * DH + d);
        float4 ux = *(const float4*)(u + h * DH + d);
        float4 vx = *(const float4*)(v + h * DH + d);
        split1(qx.x + ux.x, h0, l0); split1(qx.y + ux.y, h1, l1);
        split1(qx.z + ux.z, h2, l2); split1(qx.w + ux.w, h3, l3);
        *(__nv_bfloat162*)(g_quh + qrow)     = make_bfloat162(h0, h1);
        *(__nv_bfloat162*)(g_quh + qrow + 2) = make_bfloat162(h2, h3);
        *(__nv_bfloat162*)(g_qul + qrow)     = make_bfloat162(l0, l1);
        *(__nv_bfloat162*)(g_qul + qrow + 2) = make_bfloat162(l2, l3);
        split1(qx.x + vx.x, h0, l0); split1(qx.y + vx.y, h1, l1);
        split1(qx.z + vx.z, h2, l2); split1(qx.w + vx.w, h3, l3);
        *(__nv_bfloat162*)(g_qvh + qrow)     = make_bfloat162(h0, h1);
        *(__nv_bfloat162*)(g_qvh + qrow + 2) = make_bfloat162(h2, h3);
        *(__nv_bfloat162*)(g_qvl + qrow)     = make_bfloat162(l0, l1);
        *(__nv_bfloat162*)(g_qvl + qrow + 2) = make_bfloat162(l2, l3);
    }
}

// V transposed per head: g_vt[bh][d][j]
__global__ __launch_bounds__(256)
void split_vt()
{
    __shared__ float s[64][65];
    const int bh = blockIdx.y;
    const int b = bh >> 4;
    const int h = bh & 15;
    const int j0 = blockIdx.x * 64;
    const int t = threadIdx.x;
#pragma unroll
    for (int it = 0; it < 4; ++it) {
        int jj = it * 16 + (t >> 4);
        int d = (t & 15) * 4;
        float4 x = *(const float4*)(g_w + (size_t)(b * KL + j0 + jj) * 3072 + DM + h * DH + d);
        s[jj][d] = x.x; s[jj][d + 1] = x.y; s[jj][d + 2] = x.z; s[jj][d + 3] = x.w;
    }
    __syncthreads();
#pragma unroll
    for (int it = 0; it < 4; ++it) {
        int d = it * 16 + (t >> 4);
        int jj = (t & 15) * 4;
        size_t o = ((size_t)bh * DH + d) * KL + j0 + jj;
        __nv_bfloat16 h0, l0, h1, l1, h2, l2, h3, l3;
        split1(s[jj][d], h0, l0); split1(s[jj + 1][d], h1, l1);
        split1(s[jj + 2][d], h2, l2); split1(s[jj + 3][d], h3, l3);
        *(__nv_bfloat162*)(g_vth + o)     = make_bfloat162(h0, h1);
        *(__nv_bfloat162*)(g_vth + o + 2) = make_bfloat162(h2, h3);
        *(__nv_bfloat162*)(g_vtl + o)     = make_bfloat162(l0, l1);
        *(__nv_bfloat162*)(g_vtl + o + 2) = make_bfloat162(l2, l3);
    }
}

// ============== dense GEMM: mma.sync bf16 3-term split ======================
#define RS 80
#define ARRB (128 * RS)
#define STGB (4 * ARRB)
#define NSTG 4
#define GEMM_SMEM (NSTG * STGB)

__global__ __launch_bounds__(256, 1)
void gemm_bf3(const __nv_bfloat16* __restrict__ Ah, const __nv_bfloat16* __restrict__ Al,
              const __nv_bfloat16* __restrict__ Bh, const __nv_bfloat16* __restrict__ Bl,
              const float* __restrict__ bias, float* __restrict__ C, int N, int skipq)
{
    extern __shared__ char sm[];
    const uint32_t sb = smem_u32(sm);
    const int t = threadIdx.x;
    const int lane = t & 31;
    const int wid = t >> 5;
    const int m0 = blockIdx.y * 128;
    const int n0 = blockIdx.x * 128;
    // q columns (n < 1024 in the qkv GEMM) are unused for memory rows
    if (skipq && n0 < 1024 && ((m0 & 2047) + 128) <= ML) return;

    const int warp_m = (wid & 1) * 64;
    const int warp_n = (wid >> 1) * 32;

    const __nv_bfloat16* srcs[4] = {
        Ah + (size_t)m0 * DM, Al + (size_t)m0 * DM,
        Bh + (size_t)n0 * DM, Bl + (size_t)n0 * DM
    };

    auto issue_stage = [&](int c) {
        uint32_t dst0 = sb + (uint32_t)(c & 3) * STGB;
#pragma unroll
        for (int arr = 0; arr < 4; ++arr) {
#pragma unroll
            for (int rep = 0; rep < 2; ++rep) {
                int ci = t + rep * 256;
                int row = ci >> 2;
                int kc = ci & 3;
                uint32_t dst = dst0 + arr * ARRB + row * RS + kc * 16;
                const __nv_bfloat16* src = srcs[arr] + (size_t)row * DM + c * 32 + kc * 8;
                CP16(dst, src);
            }
        }
    };

    float acc[4][4][4];
#pragma unroll
    for (int im = 0; im < 4; ++im)
#pragma unroll
        for (int jn = 0; jn < 4; ++jn)
#pragma unroll
            for (int q = 0; q < 4; ++q) acc[im][jn][q] = 0.f;

#pragma unroll
    for (int s = 0; s < NSTG - 1; ++s) { issue_stage(s); CP_COMMIT(); }

    const int NCH = DM / 32;
    for (int c = 0; c < NCH; ++c) {
        CP_WAIT(2);
        __syncthreads();
        if (c + 3 < NCH) issue_stage(c + 3);
        CP_COMMIT();

        const uint32_t st = sb + (uint32_t)(c & 3) * STGB;
        const int mrow = lane & 15;
        const int khalf = lane >> 4;
        const int nrow = lane & 7;
        const int khalfb = (lane >> 3) & 1;
#pragma unroll
        for (int kk = 0; kk < 32; kk += 16) {
            uint32_t ah[4][4], al[4][4], bh[4][2], bl[4][2];
#pragma unroll
            for (int im = 0; im < 4; ++im) {
                uint32_t aaddr = st + (warp_m + im * 16 + mrow) * RS + (kk + khalf * 8) * 2;
                ldmx4(ah[im], aaddr);
                ldmx4(al[im], aaddr + ARRB);
            }
#pragma unroll
            for (int jn = 0; jn < 4; ++jn) {
                uint32_t baddr = st + 2 * ARRB + (warp_n + jn * 8 + nrow) * RS + (kk + khalfb * 8) * 2;
                ldmx2(bh[jn], baddr);
                ldmx2(bl[jn], baddr + ARRB);
            }
#pragma unroll
            for (int im = 0; im < 4; ++im)
#pragma unroll
                for (int jn = 0; jn < 4; ++jn) {
                    mma16816(acc[im][jn], ah[im], bh[jn]);
                    mma16816(acc[im][jn], ah[im], bl[jn]);
                    mma16816(acc[im][jn], al[im], bh[jn]);
                }
        }
    }

#pragma unroll
    for (int im = 0; im < 4; ++im) {
        int m = m0 + warp_m + im * 16 + (lane >> 2);
#pragma unroll
        for (int jn = 0; jn < 4; ++jn) {
            int n = n0 + warp_n + jn * 8 + (lane & 3) * 2;
            float b0 = bias[n], b1 = bias[n + 1];
            float2 v0, v1;
            v0.x = acc[im][jn][0] + b0; v0.y = acc[im][jn][1] + b1;
            v1.x = acc[im][jn][2] + b0; v1.y = acc[im][jn][3] + b1;
            *(float2*)(C + (size_t)m * N + n) = v0;
            *(float2*)(C + (size_t)(m + 8) * N + n) = v1;
        }
    }
}

// ============== AC / BD score GEMM (mma, K=64 single shot) ==================
// AC writes aligned tiles to g_score. BD writes PRE-SHIFTED (j = p + i - 1023)
// scalar scatters to g_bd so the flash kernel reads both with identical,
// aligned indexing. Per-row shift is bijective -> no write races.
#define SRS 144
#define SARRB (128 * SRS)
#define SCORE_SMEM (4 * SARRB)

template<bool IS_BD>
__global__ __launch_bounds__(256, 1)
void score_mma()
{
    const int bh = blockIdx.z;
    const int i0 = blockIdx.y * 128;
    const int p0 = blockIdx.x * 128;
    if (!IS_BD) {
        if (p0 > ML + i0 + 127) return;
    } else {
        if (i0 + p0 + 254 < QL - 1) return;
    }

    extern __shared__ char sm[];
    const uint32_t sb = smem_u32(sm);
    const int t = threadIdx.x;
    const int lane = t & 31;
    const int wid = t >> 5;
    const int warp_m = (wid & 1) * 64;
    const int warp_n = (wid >> 1) * 32;

    const __nv_bfloat16* srcs[4];
    if (!IS_BD) {
        srcs[0] = g_quh + ((size_t)bh * QL + i0) * DH;
        srcs[1] = g_qul + ((size_t)bh * QL + i0) * DH;
        srcs[2] = g_khh + ((size_t)bh * KL + p0) * DH;
        srcs[3] = g_khl + ((size_t)bh * KL + p0) * DH;
    } else {
        srcs[0] = g_qvh + ((size_t)bh * QL + i0) * DH;
        srcs[1] = g_qvl + ((size_t)bh * QL + i0) * DH;
        srcs[2] = g_rrh + ((size_t)bh * KL + p0) * DH;
        srcs[3] = g_rrl + ((size_t)bh * KL + p0) * DH;
    }
#pragma unroll
    for (int arr = 0; arr < 4; ++arr) {
#pragma unroll
        for (int rep = 0; rep < 4; ++rep) {
            int ci = t + rep * 256;
            int row = ci >> 3;
            int kc = ci & 7;
            uint32_t dst = sb + arr * SARRB + row * SRS + kc * 16;
            CP16(dst, srcs[arr] + (size_t)row * DH + kc * 8);
        }
    }
    CP_COMMIT();
    CP_WAIT(0);
    __syncthreads();

    float acc[4][4][4];
#pragma unroll
    for (int im = 0; im < 4; ++im)
#pragma unroll
        for (int jn = 0; jn < 4; ++jn)
#pragma unroll
            for (int q = 0; q < 4; ++q) acc[im][jn][q] = 0.f;

    const int mrow = lane & 15;
    const int khalf = lane >> 4;
    const int nrow = lane & 7;
    const int khalfb = (lane >> 3) & 1;
#pragma unroll
    for (int kk = 0; kk < 64; kk += 16) {
        uint32_t ah[4][4], al[4][4], bh[4][2], bl[4][2];
#pragma unroll
        for (int im = 0; im < 4; ++im) {
            uint32_t aaddr = sb + (warp_m + im * 16 + mrow) * SRS + (kk + khalf * 8) * 2;
            ldmx4(ah[im], aaddr);
            ldmx4(al[im], aaddr + SARRB);
        }
#pragma unroll
        for (int jn = 0; jn < 4; ++jn) {
            uint32_t baddr = sb + 2 * SARRB + (warp_n + jn * 8 + nrow) * SRS + (kk + khalfb * 8) * 2;
            ldmx2(bh[jn], baddr);
            ldmx2(bl[jn], baddr + SARRB);
        }
#pragma unroll
        for (int im = 0; im < 4; ++im)
#pragma unroll
            for (int jn = 0; jn < 4; ++jn) {
                mma16816(acc[im][jn], ah[im], bh[jn]);
                mma16816(acc[im][jn], ah[im], bl[jn]);
                mma16816(acc[im][jn], al[im], bh[jn]);
            }
    }

    if (!IS_BD) {
#pragma unroll
        for (int im = 0; im < 4; ++im) {
            int m = i0 + warp_m + im * 16 + (lane >> 2);
            float* r0 = g_score + ((size_t)bh * QL + m) * KL + p0;
            float* r1 = g_score + ((size_t)bh * QL + m + 8) * KL + p0;
#pragma unroll
            for (int jn = 0; jn < 4; ++jn) {
                int n = warp_n + jn * 8 + (lane & 3) * 2;
                *(float2*)(r0 + n) = make_float2(acc[im][jn][0], acc[im][jn][1]);
                *(float2*)(r1 + n) = make_float2(acc[im][jn][2], acc[im][jn][3]);
            }
        }
    } else {
#pragma unroll
        for (int im = 0; im < 4; ++im) {
            int m = i0 + warp_m + im * 16 + (lane >> 2);
            float* r0 = g_bd + ((size_t)bh * QL + m) * KL;
            float* r1 = g_bd + ((size_t)bh * QL + m + 8) * KL;
            int sh0 = m - (QL - 1);
            int sh1 = m + 8 - (QL - 1);
#pragma unroll
            for (int jn = 0; jn < 4; ++jn) {
                int p = p0 + warp_n + jn * 8 + (lane & 3) * 2;
                int j0a = p + sh0;
                int j1a = p + sh1;
                if (j0a >= 0)     r0[j0a]     = acc[im][jn][0];
                if (j0a + 1 >= 0) r0[j0a + 1] = acc[im][jn][1];
                if (j1a >= 0)     r1[j1a]     = acc[im][jn][2];
                if (j1a + 1 >= 0) r1[j1a + 1] = acc[im][jn][3];
            }
        }
    }
}

// ============ fused online-softmax + P@V flash kernel ======================
#define FCH 128
#define PRS2 272
#define P_BYTES (128 * PRS2)               // 34816 per P array (hi/lo)
#define V_BYTES (64 * PRS2)                // 17408 per V array
#define PV_V_OFF (2 * P_BYTES)             // 69632
#define PV_F_OFF (PV_V_OFF + 4 * V_BYTES)  // 139264
#define PV_SMEM2 (PV_F_OFF + 896 * 4)      // 142848

__global__ __launch_bounds__(256, 1)
void pv_flash()
{
    extern __shared__ char sm[];
    const uint32_t sb = smem_u32(sm);
    float* mrun = (float*)(sm + PV_F_OFF);
    float* ssum = mrun + 128;
    float* sc   = ssum + 128;
    float* redm = sc + 128;      // [2][128]
    float* reds = redm + 256;    // [2][128]

    const int bh = blockIdx.y;
    const int b = bh >> 4, h = bh & 15;
    const int i0 = blockIdx.x * 128;
    const int t = threadIdx.x, lane = t & 31, wid = t >> 5;

    // softmax role: 2 threads per row (halves of 64 j)
    const int srow = t & 127;
    const int shalf = t >> 7;
    const int gi = i0 + srow;
    const int valid = ML + gi + 1;
    const float* acr = g_score + ((size_t)bh * QL + gi) * KL;
    const float* bdr = g_bd    + ((size_t)bh * QL + gi) * KL;

    // mma role: 4 m-warps x 2 n-warps
    const int warp_m = (wid & 3) * 32;
    const int warp_n = (wid >> 2) * 32;

    if (t < 128) { mrun[t] = -1e30f; ssum[t] = 0.f; }

    const __nv_bfloat16* Vh = g_vth + (size_t)bh * DH * KL;
    const __nv_bfloat16* Vl = g_vtl + (size_t)bh * DH * KL;

    auto loadV = [&](int c) {
        uint32_t dst0 = sb + PV_V_OFF + (uint32_t)(c & 1) * (2 * V_BYTES);
#pragma unroll
        for (int rep = 0; rep < 4; ++rep) {
            int ci = t + rep * 256;
            int row = ci >> 4, kc = ci & 15;
            uint32_t o = row * PRS2 + kc * 16;
            CP16(dst0 + o, Vh + (size_t)row * KL + c * FCH + kc * 8);
            CP16(dst0 + V_BYTES + o, Vl + (size_t)row * KL + c * FCH + kc * 8);
        }
    };

    float acc[2][4][4];
#pragma unroll
    for (int im = 0; im < 2; ++im)
#pragma unroll
        for (int jn = 0; jn < 4; ++jn)
#pragma unroll
            for (int q = 0; q < 4; ++q) acc[im][jn][q] = 0.f;

    const int nch = (ML + i0 + 128) / FCH;
    loadV(0);
    CP_COMMIT();
    __syncthreads();

    for (int c = 0; c < nch; ++c) {
        const int jb = c * FCH + shalf * 64;
        float4 sv[16];
        float cm = -1e30f;
        if (jb + 63 < valid) {
#pragma unroll
            for (int q = 0; q < 16; ++q) {
                float4 a4 = *(const float4*)(acr + jb + q * 4);
                float4 b4 = *(const float4*)(bdr + jb + q * 4);
                sv[q].x = (a4.x + b4.x) * 0.125f;
                sv[q].y = (a4.y + b4.y) * 0.125f;
                sv[q].z = (a4.z + b4.z) * 0.125f;
                sv[q].w = (a4.w + b4.w) * 0.125f;
                cm = fmaxf(cm, fmaxf(fmaxf(sv[q].x, sv[q].y), fmaxf(sv[q].z, sv[q].w)));
            }
        } else {
#pragma unroll
            for (int q = 0; q < 16; ++q) {
                float* e = (float*)&sv[q];
#pragma unroll
                for (int w = 0; w < 4; ++w) {
                    int jj = jb + q * 4 + w;
                    int ji = jj < valid ? jj : valid - 1;
                    float s = (acr[ji] + bdr[ji]) * 0.125f;
                    e[w] = (jj < valid) ? s : -1e30f;
                    cm = fmaxf(cm, e[w]);
                }
            }
        }
        redm[shalf * 128 + srow] = cm;
        __syncthreads();
        const float mold = mrun[srow];
        const float mnew = fmaxf(mold, fmaxf(redm[srow], redm[128 + srow]));

        float psum = 0.f;
        const size_t poff = (size_t)srow * PRS2 + (size_t)shalf * 128;
#pragma unroll
        for (int q = 0; q < 16; ++q) {
            float p0 = __expf(sv[q].x - mnew);
            float p1 = __expf(sv[q].y - mnew);
            float p2 = __expf(sv[q].z - mnew);
            float p3 = __expf(sv[q].w - mnew);
            psum += (p0 + p1) + (p2 + p3);
            __nv_bfloat16 h0, l0, h1, l1, h2, l2, h3, l3;
            split1(p0, h0, l0); split1(p1, h1, l1);
            split1(p2, h2, l2); split1(p3, h3, l3);
            *(uint2*)(sm + poff + q * 8) = make_uint2(pack2(h0, h1), pack2(h2, h3));
            *(uint2*)(sm + P_BYTES + poff + q * 8) = make_uint2(pack2(l0, l1), pack2(l2, l3));
        }
        reds[shalf * 128 + srow] = psum;
        __syncthreads();
        if (t < 128) {
            float scale = __expf(mold - mnew);
            sc[t] = scale;
            mrun[t] = mnew;
            ssum[t] = ssum[t] * scale + reds[t] + reds[128 + t];
        }
        if (c + 1 < nch) loadV(c + 1);
        CP_COMMIT();
        CP_WAIT(1);
        __syncthreads();

        // rescale accumulators, then accumulate P@V for this chunk
        {
            const int mr = lane >> 2;
            float fA0 = sc[warp_m + mr],      fB0 = sc[warp_m + mr + 8];
            float fA1 = sc[warp_m + 16 + mr], fB1 = sc[warp_m + 24 + mr];
#pragma unroll
            for (int jn = 0; jn < 4; ++jn) {
                acc[0][jn][0] *= fA0; acc[0][jn][1] *= fA0;
                acc[0][jn][2] *= fB0; acc[0][jn][3] *= fB0;
                acc[1][jn][0] *= fA1; acc[1][jn][1] *= fA1;
                acc[1][jn][2] *= fB1; acc[1][jn][3] *= fB1;
            }
        }
        const uint32_t vst = sb + PV_V_OFF + (uint32_t)(c & 1) * (2 * V_BYTES);
        const int mrow = lane & 15, khalf = lane >> 4;
        const int nrow = lane & 7, khalfb = (lane >> 3) & 1;
#pragma unroll
        for (int kk = 0; kk < FCH; kk += 16) {
            uint32_t ah[2][4], al[2][4], bh[4][2], bl[4][2];
#pragma unroll
            for (int im = 0; im < 2; ++im) {
                uint32_t aaddr = sb + (warp_m + im * 16 + mrow) * PRS2 + (kk + khalf * 8) * 2;
                ldmx4(ah[im], aaddr);
                ldmx4(al[im], aaddr + P_BYTES);
            }
#pragma unroll
            for (int jn = 0; jn < 4; ++jn) {
                uint32_t baddr = vst + (warp_n + jn * 8 + nrow) * PRS2 + (kk + khalfb * 8) * 2;
                ldmx2(bh[jn], baddr);
                ldmx2(bl[jn], baddr + V_BYTES);
            }
#pragma unroll
            for (int im = 0; im < 2; ++im)
#pragma unroll
                for (int jn = 0; jn < 4; ++jn) {
                    mma16816(acc[im][jn], ah[im], bh[jn]);
                    mma16816(acc[im][jn], ah[im], bl[jn]);
                    mma16816(acc[im][jn], al[im], bh[jn]);
                }
        }
    }

    // epilogue: divide by softmax sum, store
    const int mr = lane >> 2;
#pragma unroll
    for (int im = 0; im < 2; ++im) {
        int r0 = warp_m + im * 16 + mr;
        float ivA = 1.f / ssum[r0];
        float ivB = 1.f / ssum[r0 + 8];
        float* o0 = g_attn + (size_t)(b * QL + i0 + r0) * DM + h * DH;
        float* o1 = o0 + (size_t)8 * DM;
#pragma unroll
        for (int jn = 0; jn < 4; ++jn) {
            int n = warp_n + jn * 8 + (lane & 3) * 2;
            *(float2*)(o0 + n) = make_float2(acc[im][jn][0] * ivA, acc[im][jn][1] * ivA);
            *(float2*)(o1 + n) = make_float2(acc[im][jn][2] * ivB, acc[im][jn][3] * ivB);
        }
    }
}

// =========================== launch =======================================
extern "C" void kernel_launch(void* const* d_in, const int* in_sizes, int n_in,
                              void* d_out, int out_size)
{
    const float* inputs = (const float*)d_in[0];
    const float* mem    = (const float*)d_in[1];
    const float* r      = (const float*)d_in[2];
    const float* W_qkv  = (const float*)d_in[3];
    const float* b_qkv  = (const float*)d_in[4];
    const float* W_r    = (const float*)d_in[5];
    const float* b_r    = (const float*)d_in[6];
    const float* W_o    = (const float*)d_in[7];
    const float* b_o    = (const float*)d_in[8];
    const float* u      = (const float*)d_in[9];
    const float* v      = (const float*)d_in[10];
    float* out = (float*)d_out;

    float *pw, *prp, *pattn;
    __nv_bfloat16 *pah, *pal, *prh, *prl, *poh, *pol;
    __nv_bfloat16 *pwqh, *pwql, *pwrh, *pwrl, *pwoh, *pwol;
    cudaGetSymbolAddress((void**)&pw,    g_w);
    cudaGetSymbolAddress((void**)&prp,   g_rp);
    cudaGetSymbolAddress((void**)&pattn, g_attn);
    cudaGetSymbolAddress((void**)&pah,   g_ah);
    cudaGetSymbolAddress((void**)&pal,   g_al);
    cudaGetSymbolAddress((void**)&prh,   g_rh);
    cudaGetSymbolAddress((void**)&prl,   g_rl);
    cudaGetSymbolAddress((void**)&poh,   g_oh);
    cudaGetSymbolAddress((void**)&pol,   g_ol);
    cudaGetSymbolAddress((void**)&pwqh,  g_wqh);
    cudaGetSymbolAddress((void**)&pwql,  g_wql);
    cudaGetSymbolAddress((void**)&pwrh,  g_wrh);
    cudaGetSymbolAddress((void**)&pwrl,  g_wrl);
    cudaGetSymbolAddress((void**)&pwoh,  g_woh);
    cudaGetSymbolAddress((void**)&pwol,  g_wol);

    cudaFuncSetAttribute(gemm_bf3, cudaFuncAttributeMaxDynamicSharedMemorySize, GEMM_SMEM);
    cudaFuncSetAttribute(score_mma<false>, cudaFuncAttributeMaxDynamicSharedMemorySize, SCORE_SMEM);
    cudaFuncSetAttribute(score_mma<true>,  cudaFuncAttributeMaxDynamicSharedMemorySize, SCORE_SMEM);
    cudaFuncSetAttribute(pv_flash, cudaFuncAttributeMaxDynamicSharedMemorySize, PV_SMEM2);

    dim3 blk(256);

    // --- dense GEMM input splits ---
    split_concat<<<4096, blk>>>(mem, inputs, pah, pal);
    split_plain<<<4096, blk>>>(r, prh, prl);
    split_transpose<<<dim3(3072 / 32, 1024 / 32), blk>>>(W_qkv, pwqh, pwql, 3072);
    split_transpose<<<dim3(1024 / 32, 1024 / 32), blk>>>(W_r,   pwrh, pwrl, 1024);
    split_transpose<<<dim3(1024 / 32, 1024 / 32), blk>>>(W_o,   pwoh, pwol, 1024);

    // 1) w = cat @ W_qkv + b_qkv (skip q cols for memory rows) ; 2) rp = r @ W_r
    gemm_bf3<<<dim3(3072 / 128, 4096 / 128), blk, GEMM_SMEM>>>(pah, pal, pwqh, pwql, b_qkv, pw, 3072, 1);
    gemm_bf3<<<dim3(1024 / 128, 4096 / 128), blk, GEMM_SMEM>>>(prh, prl, pwrh, pwrl, b_r, prp, 1024, 0);

    // --- per-head attention operand splits ---
    split_heads<<<4096, blk>>>(u, v);
    split_vt<<<dim3(KL / 64, BQ * NH), blk>>>();

    // 3) AC -> g_score ; 4) BD (pre-shifted) -> g_bd
    score_mma<false><<<dim3(KL / 128, QL / 128, BQ * NH), blk, SCORE_SMEM>>>();
    score_mma<true><<<dim3(KL / 128, QL / 128, BQ * NH), blk, SCORE_SMEM>>>();

    // 5+6) fused online softmax + P@V -> g_attn
    pv_flash<<<dim3(QL / 128, BQ * NH), blk, PV_SMEM2>>>();

    // 7) final projection
    split_plain<<<2048, blk>>>(pattn, poh, pol);
    gemm_bf3<<<dim3(1024 / 128, 2048 / 128), blk, GEMM_SMEM>>>(poh, pol, pwoh, pwol, b_o, out, 1024, 0);
}

// round 7
// speedup vs baseline: 1.2178x; 1.2178x over previous
#include <cuda_runtime.h>
#include <cuda_bf16.h>
#include <cstdint>
#include <cstddef>

#define BQ 2
#define QL 1024
#define ML 1024
#define KL 2048
#define DM 1024
#define NH 16
#define DH 64

// ---------------- scratch (device globals: allocation-free) ----------------
__device__ float g_w[(size_t)4096 * 3072];          // cat @ W_qkv  [B*K, 3D]
__device__ float g_rp[(size_t)4096 * 1024];         // r @ W_r      [B*K, D]
__device__ float g_bd[(size_t)32 * 1024 * 2048];    // BD (pre-shifted) [B*H, Q, K]
__device__ float g_attn[(size_t)2048 * 1024];       // [B*Q, D]

// dense GEMM bf16 hi/lo splits
__device__ __nv_bfloat16 g_ah[(size_t)4096 * 1024], g_al[(size_t)4096 * 1024];
__device__ __nv_bfloat16 g_rh[(size_t)4096 * 1024], g_rl[(size_t)4096 * 1024];
__device__ __nv_bfloat16 g_oh[(size_t)2048 * 1024], g_ol[(size_t)2048 * 1024];
__device__ __nv_bfloat16 g_wqh[(size_t)3072 * 1024], g_wql[(size_t)3072 * 1024];
__device__ __nv_bfloat16 g_wrh[(size_t)1024 * 1024], g_wrl[(size_t)1024 * 1024];
__device__ __nv_bfloat16 g_woh[(size_t)1024 * 1024], g_wol[(size_t)1024 * 1024];

// per-head attention operands (bf16 hi/lo)
__device__ __nv_bfloat16 g_quh[(size_t)32 * 1024 * 64], g_qul[(size_t)32 * 1024 * 64];
__device__ __nv_bfloat16 g_qvh[(size_t)32 * 1024 * 64], g_qvl[(size_t)32 * 1024 * 64];
__device__ __nv_bfloat16 g_khh[(size_t)32 * 2048 * 64], g_khl[(size_t)32 * 2048 * 64];
__device__ __nv_bfloat16 g_rrh[(size_t)32 * 2048 * 64], g_rrl[(size_t)32 * 2048 * 64];
__device__ __nv_bfloat16 g_vth[(size_t)32 * 64 * 2048], g_vtl[(size_t)32 * 64 * 2048];

// ======================= helpers ===========================================
__device__ __forceinline__ uint32_t smem_u32(const void* p) {
    uint32_t a;
    asm("{ .reg .u64 t; cvta.to.shared.u64 t, %1; cvt.u32.u64 %0, t; }"
        : "=r"(a) : "l"(p));
    return a;
}
__device__ __forceinline__ void split1(float x, __nv_bfloat16& h, __nv_bfloat16& l) {
    h = __float2bfloat16_rn(x);
    l = __float2bfloat16_rn(x - __bfloat162float(h));
}
__device__ __forceinline__ uint32_t pack2(__nv_bfloat16 a, __nv_bfloat16 b) {
    __nv_bfloat162 v = make_bfloat162(a, b);
    return *(uint32_t*)&v;
}
__device__ __forceinline__ void ldmx4(uint32_t a[4], uint32_t addr) {
    asm volatile("ldmatrix.sync.aligned.m8n8.x4.shared.b16 {%0,%1,%2,%3}, [%4];"
        : "=r"(a[0]), "=r"(a[1]), "=r"(a[2]), "=r"(a[3]) : "r"(addr));
}
__device__ __forceinline__ void ldmx2(uint32_t a[2], uint32_t addr) {
    asm volatile("ldmatrix.sync.aligned.m8n8.x2.shared.b16 {%0,%1}, [%2];"
        : "=r"(a[0]), "=r"(a[1]) : "r"(addr));
}
__device__ __forceinline__ void mma16816(float c[4], const uint32_t a[4], const uint32_t b[2]) {
    asm volatile("mma.sync.aligned.m16n8k16.row.col.f32.bf16.bf16.f32 "
        "{%0,%1,%2,%3}, {%4,%5,%6,%7}, {%8,%9}, {%0,%1,%2,%3};"
        : "+f"(c[0]), "+f"(c[1]), "+f"(c[2]), "+f"(c[3])
        : "r"(a[0]), "r"(a[1]), "r"(a[2]), "r"(a[3]), "r"(b[0]), "r"(b[1]));
}
#define CP16(dst, src) \
    asm volatile("cp.async.cg.shared.global [%0], [%1], 16;" :: "r"(dst), "l"(src) : "memory")
#define CP_COMMIT() asm volatile("cp.async.commit_group;" ::: "memory")
#define CP_WAIT(n)  asm volatile("cp.async.wait_group %0;" :: "n"(n) : "memory")

// ===================== prep: split kernels ==================================
__global__ __launch_bounds__(256)
void split_concat(const float* __restrict__ mem, const float* __restrict__ inp,
                  __nv_bfloat16* __restrict__ hi, __nv_bfloat16* __restrict__ lo)
{
    size_t idx = ((size_t)blockIdx.x * 256 + threadIdx.x) * 4;
    size_t row = idx >> 10;
    int col = (int)(idx & 1023);
    int b = (int)(row >> 11);
    int k = (int)(row & 2047);
    const float* src = (k < ML) ? mem + ((size_t)(b * ML + k) << 10)
                                : inp + ((size_t)(b * QL + (k - ML)) << 10);
    float4 v = *(const float4*)(src + col);
    __nv_bfloat16 h0, h1, h2, h3, l0, l1, l2, l3;
    split1(v.x, h0, l0); split1(v.y, h1, l1);
    split1(v.z, h2, l2); split1(v.w, h3, l3);
    __nv_bfloat162* H = (__nv_bfloat162*)(hi + idx);
    __nv_bfloat162* L = (__nv_bfloat162*)(lo + idx);
    H[0] = make_bfloat162(h0, h1); H[1] = make_bfloat162(h2, h3);
    L[0] = make_bfloat162(l0, l1); L[1] = make_bfloat162(l2, l3);
}

__global__ __launch_bounds__(256)
void split_plain(const float* __restrict__ src,
                 __nv_bfloat16* __restrict__ hi, __nv_bfloat16* __restrict__ lo)
{
    size_t idx = ((size_t)blockIdx.x * 256 + threadIdx.x) * 4;
    float4 v = *(const float4*)(src + idx);
    __nv_bfloat16 h0, h1, h2, h3, l0, l1, l2, l3;
    split1(v.x, h0, l0); split1(v.y, h1, l1);
    split1(v.z, h2, l2); split1(v.w, h3, l3);
    __nv_bfloat162* H = (__nv_bfloat162*)(hi + idx);
    __nv_bfloat162* L = (__nv_bfloat162*)(lo + idx);
    H[0] = make_bfloat162(h0, h1); H[1] = make_bfloat162(h2, h3);
    L[0] = make_bfloat162(l0, l1); L[1] = make_bfloat162(l2, l3);
}

__global__ __launch_bounds__(256)
void split_transpose(const float* __restrict__ in,
                     __nv_bfloat16* __restrict__ hi, __nv_bfloat16* __restrict__ lo, int N)
{
    __shared__ float s[32][33];
    const int nx = blockIdx.x * 32;
    const int ky = blockIdx.y * 32;
    const int tx = threadIdx.x & 31;
    const int ty = threadIdx.x >> 5;
#pragma unroll
    for (int r = 0; r < 32; r += 8)
        s[ty + r][tx] = in[(size_t)(ky + ty + r) * N + nx + tx];
    __syncthreads();
#pragma unroll
    for (int r = 0; r < 32; r += 8) {
        float x = s[tx][ty + r];
        __nv_bfloat16 h, l;
        split1(x, h, l);
        size_t o = (size_t)(nx + ty + r) * DM + ky + tx;
        hi[o] = h;
        lo[o] = l;
    }
}

// per-head operands: qu/qv (rows i), k/r (rows j), all [bh][row][64] K-major
__global__ __launch_bounds__(256)
void split_heads(const float* __restrict__ u, const float* __restrict__ v)
{
    size_t gid = (size_t)blockIdx.x * 256 + threadIdx.x;
    int d = (int)(gid & 15) * 4;
    int h = (int)(gid >> 4) & 15;
    int j = (int)(gid >> 8) & 2047;
    int b = (int)(gid >> 19);
    size_t wrow = (size_t)(b * KL + j);
    size_t orow = ((size_t)(b * NH + h) * KL + j) * DH + d;

    float4 kx = *(const float4*)(g_w + wrow * 3072 + 2 * DM + h * DH + d);
    float4 rx = *(const float4*)(g_rp + wrow * DM + h * DH + d);
    __nv_bfloat16 h0, l0, h1, l1, h2, l2, h3, l3;
    split1(kx.x, h0, l0); split1(kx.y, h1, l1); split1(kx.z, h2, l2); split1(kx.w, h3, l3);
    *(__nv_bfloat162*)(g_khh + orow)     = make_bfloat162(h0, h1);
    *(__nv_bfloat162*)(g_khh + orow + 2) = make_bfloat162(h2, h3);
    *(__nv_bfloat162*)(g_khl + orow)     = make_bfloat162(l0, l1);
    *(__nv_bfloat162*)(g_khl + orow + 2) = make_bfloat162(l2, l3);
    split1(rx.x, h0, l0); split1(rx.y, h1, l1); split1(rx.z, h2, l2); split1(rx.w, h3, l3);
    *(__nv_bfloat162*)(g_rrh + orow)     = make_bfloat162(h0, h1);
    *(__nv_bfloat162*)(g_rrh + orow + 2) = make_bfloat162(h2, h3);
    *(__nv_bfloat162*)(g_rrl + orow)     = make_bfloat162(l0, l1);
    *(__nv_bfloat162*)(g_rrl + orow + 2) = make_bfloat162(l2, l3);

    if (j >= ML) {
        int i = j - ML;
        size_t qrow = ((size_t)(b * NH + h) * QL + i) * DH + d;
        float4 qx = *(const float4*)(g_w + wrow * 3072 + h * DH + d);
        float4 ux = *(const float4*)(u + h * DH + d);
        float4 vx = *(const float4*)(v + h * DH + d);
        split1(qx.x + ux.x, h0, l0); split1(qx.y + ux.y, h1, l1);
        split1(qx.z + ux.z, h2, l2); split1(qx.w + ux.w, h3, l3);
        *(__nv_bfloat162*)(g_quh + qrow)     = make_bfloat162(h0, h1);
        *(__nv_bfloat162*)(g_quh + qrow + 2) = make_bfloat162(h2, h3);
        *(__nv_bfloat162*)(g_qul + qrow)     = make_bfloat162(l0, l1);
        *(__nv_bfloat162*)(g_qul + qrow + 2) = make_bfloat162(l2, l3);
        split1(qx.x + vx.x, h0, l0); split1(qx.y + vx.y, h1, l1);
        split1(qx.z + vx.z, h2, l2); split1(qx.w + vx.w, h3, l3);
        *(__nv_bfloat162*)(g_qvh + qrow)     = make_bfloat162(h0, h1);
        *(__nv_bfloat162*)(g_qvh + qrow + 2) = make_bfloat162(h2, h3);
        *(__nv_bfloat162*)(g_qvl + qrow)     = make_bfloat162(l0, l1);
        *(__nv_bfloat162*)(g_qvl + qrow + 2) = make_bfloat162(l2, l3);
    }
}

// V transposed per head: g_vt[bh][d][j]
__global__ __launch_bounds__(256)
void split_vt()
{
    __shared__ float s[64][65];
    const int bh = blockIdx.y;
    const int b = bh >> 4;
    const int h = bh & 15;
    const int j0 = blockIdx.x * 64;
    const int t = threadIdx.x;
#pragma unroll
    for (int it = 0; it < 4; ++it) {
        int jj = it * 16 + (t >> 4);
        int d = (t & 15) * 4;
        float4 x = *(const float4*)(g_w + (size_t)(b * KL + j0 + jj) * 3072 + DM + h * DH + d);
        s[jj][d] = x.x; s[jj][d + 1] = x.y; s[jj][d + 2] = x.z; s[jj][d + 3] = x.w;
    }
    __syncthreads();
#pragma unroll
    for (int it = 0; it < 4; ++it) {
        int d = it * 16 + (t >> 4);
        int jj = (t & 15) * 4;
        size_t o = ((size_t)bh * DH + d) * KL + j0 + jj;
        __nv_bfloat16 h0, l0, h1, l1, h2, l2, h3, l3;
        split1(s[jj][d], h0, l0); split1(s[jj + 1][d], h1, l1);
        split1(s[jj + 2][d], h2, l2); split1(s[jj + 3][d], h3, l3);
        *(__nv_bfloat162*)(g_vth + o)     = make_bfloat162(h0, h1);
        *(__nv_bfloat162*)(g_vth + o + 2) = make_bfloat162(h2, h3);
        *(__nv_bfloat162*)(g_vtl + o)     = make_bfloat162(l0, l1);
        *(__nv_bfloat162*)(g_vtl + o + 2) = make_bfloat162(l2, l3);
    }
}

// ============== dense GEMM: mma.sync bf16 3-term split ======================
#define RS 80
#define ARRB (128 * RS)
#define STGB (4 * ARRB)
#define NSTG 4
#define GEMM_SMEM (NSTG * STGB)

__global__ __launch_bounds__(256, 1)
void gemm_bf3(const __nv_bfloat16* __restrict__ Ah, const __nv_bfloat16* __restrict__ Al,
              const __nv_bfloat16* __restrict__ Bh, const __nv_bfloat16* __restrict__ Bl,
              const float* __restrict__ bias, float* __restrict__ C, int N, int skipq)
{
    extern __shared__ char sm[];
    const uint32_t sb = smem_u32(sm);
    const int t = threadIdx.x;
    const int lane = t & 31;
    const int wid = t >> 5;
    const int m0 = blockIdx.y * 128;
    const int n0 = blockIdx.x * 128;
    if (skipq && n0 < 1024 && ((m0 & 2047) + 128) <= ML) return;

    const int warp_m = (wid & 1) * 64;
    const int warp_n = (wid >> 1) * 32;

    const __nv_bfloat16* srcs[4] = {
        Ah + (size_t)m0 * DM, Al + (size_t)m0 * DM,
        Bh + (size_t)n0 * DM, Bl + (size_t)n0 * DM
    };

    auto issue_stage = [&](int c) {
        uint32_t dst0 = sb + (uint32_t)(c & 3) * STGB;
#pragma unroll
        for (int arr = 0; arr < 4; ++arr) {
#pragma unroll
            for (int rep = 0; rep < 2; ++rep) {
                int ci = t + rep * 256;
                int row = ci >> 2;
                int kc = ci & 3;
                uint32_t dst = dst0 + arr * ARRB + row * RS + kc * 16;
                const __nv_bfloat16* src = srcs[arr] + (size_t)row * DM + c * 32 + kc * 8;
                CP16(dst, src);
            }
        }
    };

    float acc[4][4][4];
#pragma unroll
    for (int im = 0; im < 4; ++im)
#pragma unroll
        for (int jn = 0; jn < 4; ++jn)
#pragma unroll
            for (int q = 0; q < 4; ++q) acc[im][jn][q] = 0.f;

#pragma unroll
    for (int s = 0; s < NSTG - 1; ++s) { issue_stage(s); CP_COMMIT(); }

    const int NCH = DM / 32;
    for (int c = 0; c < NCH; ++c) {
        CP_WAIT(2);
        __syncthreads();
        if (c + 3 < NCH) issue_stage(c + 3);
        CP_COMMIT();

        const uint32_t st = sb + (uint32_t)(c & 3) * STGB;
        const int mrow = lane & 15;
        const int khalf = lane >> 4;
        const int nrow = lane & 7;
        const int khalfb = (lane >> 3) & 1;
#pragma unroll
        for (int kk = 0; kk < 32; kk += 16) {
            uint32_t ah[4][4], al[4][4], bh[4][2], bl[4][2];
#pragma unroll
            for (int im = 0; im < 4; ++im) {
                uint32_t aaddr = st + (warp_m + im * 16 + mrow) * RS + (kk + khalf * 8) * 2;
                ldmx4(ah[im], aaddr);
                ldmx4(al[im], aaddr + ARRB);
            }
#pragma unroll
            for (int jn = 0; jn < 4; ++jn) {
                uint32_t baddr = st + 2 * ARRB + (warp_n + jn * 8 + nrow) * RS + (kk + khalfb * 8) * 2;
                ldmx2(bh[jn], baddr);
                ldmx2(bl[jn], baddr + ARRB);
            }
#pragma unroll
            for (int im = 0; im < 4; ++im)
#pragma unroll
                for (int jn = 0; jn < 4; ++jn) {
                    mma16816(acc[im][jn], ah[im], bh[jn]);
                    mma16816(acc[im][jn], ah[im], bl[jn]);
                    mma16816(acc[im][jn], al[im], bh[jn]);
                }
        }
    }

#pragma unroll
    for (int im = 0; im < 4; ++im) {
        int m = m0 + warp_m + im * 16 + (lane >> 2);
#pragma unroll
        for (int jn = 0; jn < 4; ++jn) {
            int n = n0 + warp_n + jn * 8 + (lane & 3) * 2;
            float b0 = bias[n], b1 = bias[n + 1];
            float2 v0, v1;
            v0.x = acc[im][jn][0] + b0; v0.y = acc[im][jn][1] + b1;
            v1.x = acc[im][jn][2] + b0; v1.y = acc[im][jn][3] + b1;
            *(float2*)(C + (size_t)m * N + n) = v0;
            *(float2*)(C + (size_t)(m + 8) * N + n) = v1;
        }
    }
}

// ============== BD score GEMM (mma, K=64, pre-shifted scatter) ==============
#define SRS 144
#define SARRB (128 * SRS)
#define SCORE_SMEM (4 * SARRB)

__global__ __launch_bounds__(256, 1)
void bd_mma()
{
    const int bh = blockIdx.z;
    const int i0 = blockIdx.y * 128;
    const int p0 = blockIdx.x * 128;
    if (i0 + p0 + 254 < QL - 1) return;

    extern __shared__ char sm[];
    const uint32_t sb = smem_u32(sm);
    const int t = threadIdx.x;
    const int lane = t & 31;
    const int wid = t >> 5;
    const int warp_m = (wid & 1) * 64;
    const int warp_n = (wid >> 1) * 32;

    const __nv_bfloat16* srcs[4] = {
        g_qvh + ((size_t)bh * QL + i0) * DH,
        g_qvl + ((size_t)bh * QL + i0) * DH,
        g_rrh + ((size_t)bh * KL + p0) * DH,
        g_rrl + ((size_t)bh * KL + p0) * DH
    };
#pragma unroll
    for (int arr = 0; arr < 4; ++arr) {
#pragma unroll
        for (int rep = 0; rep < 4; ++rep) {
            int ci = t + rep * 256;
            int row = ci >> 3;
            int kc = ci & 7;
            uint32_t dst = sb + arr * SARRB + row * SRS + kc * 16;
            CP16(dst, srcs[arr] + (size_t)row * DH + kc * 8);
        }
    }
    CP_COMMIT();
    CP_WAIT(0);
    __syncthreads();

    float acc[4][4][4];
#pragma unroll
    for (int im = 0; im < 4; ++im)
#pragma unroll
        for (int jn = 0; jn < 4; ++jn)
#pragma unroll
            for (int q = 0; q < 4; ++q) acc[im][jn][q] = 0.f;

    const int mrow = lane & 15;
    const int khalf = lane >> 4;
    const int nrow = lane & 7;
    const int khalfb = (lane >> 3) & 1;
#pragma unroll
    for (int kk = 0; kk < 64; kk += 16) {
        uint32_t ah[4][4], al[4][4], bh[4][2], bl[4][2];
#pragma unroll
        for (int im = 0; im < 4; ++im) {
            uint32_t aaddr = sb + (warp_m + im * 16 + mrow) * SRS + (kk + khalf * 8) * 2;
            ldmx4(ah[im], aaddr);
            ldmx4(al[im], aaddr + SARRB);
        }
#pragma unroll
        for (int jn = 0; jn < 4; ++jn) {
            uint32_t baddr = sb + 2 * SARRB + (warp_n + jn * 8 + nrow) * SRS + (kk + khalfb * 8) * 2;
            ldmx2(bh[jn], baddr);
            ldmx2(bl[jn], baddr + SARRB);
        }
#pragma unroll
        for (int im = 0; im < 4; ++im)
#pragma unroll
            for (int jn = 0; jn < 4; ++jn) {
                mma16816(acc[im][jn], ah[im], bh[jn]);
                mma16816(acc[im][jn], ah[im], bl[jn]);
                mma16816(acc[im][jn], al[im], bh[jn]);
            }
    }

#pragma unroll
    for (int im = 0; im < 4; ++im) {
        int m = i0 + warp_m + im * 16 + (lane >> 2);
        float* r0 = g_bd + ((size_t)bh * QL + m) * KL;
        float* r1 = g_bd + ((size_t)bh * QL + m + 8) * KL;
        int sh0 = m - (QL - 1);
        int sh1 = m + 8 - (QL - 1);
#pragma unroll
        for (int jn = 0; jn < 4; ++jn) {
            int p = p0 + warp_n + jn * 8 + (lane & 3) * 2;
            int j0a = p + sh0;
            int j1a = p + sh1;
            if (j0a >= 0)     r0[j0a]     = acc[im][jn][0];
            if (j0a + 1 >= 0) r0[j0a + 1] = acc[im][jn][1];
            if (j1a >= 0)     r1[j1a]     = acc[im][jn][2];
            if (j1a + 1 >= 0) r1[j1a + 1] = acc[im][jn][3];
        }
    }
}

// ========== warp-autonomous flash attention: AC in-register + PV ===========
// per CTA: 128 rows, 8 warps x 16 rows. j-chunks of 128.
// smem: Q (hi/lo, 36864) | K double-buffered (2x36864) | V double-buffered (2x34816)
#define FCH 128
#define AQ_OFF 0u
#define AK_OFF 36864u
#define AV_OFF 110592u
#define ATTN_SMEM 180224

__global__ __launch_bounds__(256, 1)
void attn_flash()
{
    extern __shared__ char sm[];
    const uint32_t sb = smem_u32(sm);
    const int bh = blockIdx.y;
    const int b = bh >> 4, h = bh & 15;
    const int i0 = blockIdx.x * 128;
    const int t = threadIdx.x, lane = t & 31, wid = t >> 5;
    const int warp_m = wid * 16;

    const __nv_bfloat16* Kh = g_khh + (size_t)bh * KL * DH;
    const __nv_bfloat16* Klo = g_khl + (size_t)bh * KL * DH;
    const __nv_bfloat16* Vh = g_vth + (size_t)bh * DH * KL;
    const __nv_bfloat16* Vl = g_vtl + (size_t)bh * DH * KL;

    // Q tile load (hi/lo)
    {
        const __nv_bfloat16* Qh = g_quh + ((size_t)bh * QL + i0) * DH;
        const __nv_bfloat16* Ql = g_qul + ((size_t)bh * QL + i0) * DH;
#pragma unroll
        for (int rep = 0; rep < 4; ++rep) {
            int ci = t + rep * 256;
            int row = ci >> 3, kc = ci & 7;
            uint32_t dst = sb + AQ_OFF + row * SRS + kc * 16;
            CP16(dst, Qh + (size_t)row * DH + kc * 8);
            CP16(dst + 18432u, Ql + (size_t)row * DH + kc * 8);
        }
    }
    CP_COMMIT();

    auto loadKV = [&](int c) {
        uint32_t kd = sb + AK_OFF + (uint32_t)(c & 1) * 36864u;
#pragma unroll
        for (int rep = 0; rep < 4; ++rep) {
            int ci = t + rep * 256;
            int row = ci >> 3, kc = ci & 7;
            uint32_t dst = kd + row * SRS + kc * 16;
            CP16(dst, Kh + (size_t)(c * FCH + row) * DH + kc * 8);
            CP16(dst + 18432u, Klo + (size_t)(c * FCH + row) * DH + kc * 8);
        }
        uint32_t vd = sb + AV_OFF + (uint32_t)(c & 1) * 34816u;
#pragma unroll
        for (int rep = 0; rep < 4; ++rep) {
            int ci = t + rep * 256;
            int row = ci >> 4, kc = ci & 15;
            uint32_t dst = vd + row * 272 + kc * 16;
            CP16(dst, Vh + (size_t)row * KL + c * FCH + kc * 8);
            CP16(dst + 17408u, Vl + (size_t)row * KL + c * FCH + kc * 8);
        }
    };

    const int nch = (ML + i0 + 128) / FCH;   // >= 9 always
    loadKV(0); CP_COMMIT();
    loadKV(1); CP_COMMIT();

    // Q A-fragments cached in registers
    const int mrow = lane & 15, khalf = lane >> 4;
    const int nrow = lane & 7, khalfb = (lane >> 3) & 1;
    uint32_t aqh[4][4], aql[4][4];
    CP_WAIT(2);
    __syncthreads();
#pragma unroll
    for (int kf = 0; kf < 4; ++kf) {
        uint32_t aaddr = sb + AQ_OFF + (warp_m + mrow) * SRS + (kf * 16 + khalf * 8) * 2;
        ldmx4(aqh[kf], aaddr);
        ldmx4(aql[kf], aaddr + 18432u);
    }

    const int r0 = lane >> 2;
    const int colb = (lane & 3) * 2;
    const float* bdr0 = g_bd + ((size_t)bh * QL + i0 + warp_m + r0) * KL;
    const float* bdr1 = bdr0 + (size_t)8 * KL;
    const int lim0 = ML + i0 + warp_m + r0;   // max valid j (inclusive) for row r0
    const int lim1 = lim0 + 8;

    float pvacc[8][4];
#pragma unroll
    for (int nf = 0; nf < 8; ++nf)
#pragma unroll
        for (int q = 0; q < 4; ++q) pvacc[nf][q] = 0.f;
    float ssum0 = 0.f, ssum1 = 0.f;
    float mold0 = -1e30f, mold1 = -1e30f;

    for (int c = 0; c < nch; ++c) {
        CP_WAIT(1);
        __syncthreads();
        const uint32_t kst = sb + AK_OFF + (uint32_t)(c & 1) * 36864u;
        const uint32_t vst = sb + AV_OFF + (uint32_t)(c & 1) * 34816u;
        const int j0 = c * FCH;

        // ---- S = (q+u) . K^T  (16 x 128 per warp, in accumulators) ----
        float S[16][4];
#pragma unroll
        for (int nf = 0; nf < 16; ++nf) {
            S[nf][0] = S[nf][1] = S[nf][2] = S[nf][3] = 0.f;
#pragma unroll
            for (int kf = 0; kf < 4; ++kf) {
                uint32_t bhh[2], bll[2];
                uint32_t baddr = kst + (nf * 8 + nrow) * SRS + (kf * 16 + khalfb * 8) * 2;
                ldmx2(bhh, baddr);
                ldmx2(bll, baddr + 18432u);
                mma16816(S[nf], aqh[kf], bhh);
                mma16816(S[nf], aqh[kf], bll);
                mma16816(S[nf], aql[kf], bhh);
            }
        }

        // ---- + BD (pre-shifted, aligned rows), scale, mask, row max ----
        const bool nomask = (j0 + 127) <= lim0;
        float mx0 = -1e30f, mx1 = -1e30f;
#pragma unroll
        for (int nf = 0; nf < 16; ++nf) {
            int jc = j0 + nf * 8 + colb;
            float2 b0 = *(const float2*)(bdr0 + jc);
            float2 b1 = *(const float2*)(bdr1 + jc);
            float s0 = (S[nf][0] + b0.x) * 0.125f;
            float s1 = (S[nf][1] + b0.y) * 0.125f;
            float s2 = (S[nf][2] + b1.x) * 0.125f;
            float s3 = (S[nf][3] + b1.y) * 0.125f;
            if (!nomask) {
                s0 = (jc     <= lim0) ? s0 : -1e30f;
                s1 = (jc + 1 <= lim0) ? s1 : -1e30f;
                s2 = (jc     <= lim1) ? s2 : -1e30f;
                s3 = (jc + 1 <= lim1) ? s3 : -1e30f;
            }
            S[nf][0] = s0; S[nf][1] = s1; S[nf][2] = s2; S[nf][3] = s3;
            mx0 = fmaxf(mx0, fmaxf(s0, s1));
            mx1 = fmaxf(mx1, fmaxf(s2, s3));
        }
        mx0 = fmaxf(mx0, __shfl_xor_sync(0xffffffffu, mx0, 1));
        mx0 = fmaxf(mx0, __shfl_xor_sync(0xffffffffu, mx0, 2));
        mx1 = fmaxf(mx1, __shfl_xor_sync(0xffffffffu, mx1, 1));
        mx1 = fmaxf(mx1, __shfl_xor_sync(0xffffffffu, mx1, 2));
        const float mnew0 = fmaxf(mold0, mx0);
        const float mnew1 = fmaxf(mold1, mx1);
        const float sc0 = __expf(mold0 - mnew0);
        const float sc1 = __expf(mold1 - mnew1);
        mold0 = mnew0; mold1 = mnew1;
        ssum0 *= sc0; ssum1 *= sc1;
#pragma unroll
        for (int nf = 0; nf < 8; ++nf) {
            pvacc[nf][0] *= sc0; pvacc[nf][1] *= sc0;
            pvacc[nf][2] *= sc1; pvacc[nf][3] *= sc1;
        }
#pragma unroll
        for (int nf = 0; nf < 16; ++nf) {
            S[nf][0] = __expf(S[nf][0] - mnew0);
            S[nf][1] = __expf(S[nf][1] - mnew0);
            S[nf][2] = __expf(S[nf][2] - mnew1);
            S[nf][3] = __expf(S[nf][3] - mnew1);
            ssum0 += S[nf][0] + S[nf][1];
            ssum1 += S[nf][2] + S[nf][3];
        }

        // ---- P (bf16 hi/lo, C-frag -> A-frag identity) @ V ----
#pragma unroll
        for (int kf = 0; kf < 8; ++kf) {
            uint32_t pah[4], pal[4];
            __nv_bfloat16 h0, l0, h1, l1;
            split1(S[2 * kf][0], h0, l0);     split1(S[2 * kf][1], h1, l1);
            pah[0] = pack2(h0, h1);           pal[0] = pack2(l0, l1);
            split1(S[2 * kf][2], h0, l0);     split1(S[2 * kf][3], h1, l1);
            pah[1] = pack2(h0, h1);           pal[1] = pack2(l0, l1);
            split1(S[2 * kf + 1][0], h0, l0); split1(S[2 * kf + 1][1], h1, l1);
            pah[2] = pack2(h0, h1);           pal[2] = pack2(l0, l1);
            split1(S[2 * kf + 1][2], h0, l0); split1(S[2 * kf + 1][3], h1, l1);
            pah[3] = pack2(h0, h1);           pal[3] = pack2(l0, l1);
#pragma unroll
            for (int nf = 0; nf < 8; ++nf) {
                uint32_t bhh[2], bll[2];
                uint32_t baddr = vst + (nf * 8 + nrow) * 272 + (kf * 16 + khalfb * 8) * 2;
                ldmx2(bhh, baddr);
                ldmx2(bll, baddr + 17408u);
                mma16816(pvacc[nf], pah, bhh);
                mma16816(pvacc[nf], pah, bll);
                mma16816(pvacc[nf], pal, bhh);
            }
        }

        __syncthreads();
        if (c + 2 < nch) loadKV(c + 2);
        CP_COMMIT();
    }

    // ---- epilogue: row sums via quad reduce, normalize, store ----
    ssum0 += __shfl_xor_sync(0xffffffffu, ssum0, 1);
    ssum0 += __shfl_xor_sync(0xffffffffu, ssum0, 2);
    ssum1 += __shfl_xor_sync(0xffffffffu, ssum1, 1);
    ssum1 += __shfl_xor_sync(0xffffffffu, ssum1, 2);
    const float iv0 = 1.f / ssum0;
    const float iv1 = 1.f / ssum1;
    float* o0 = g_attn + (size_t)(b * QL + i0 + warp_m + r0) * DM + h * DH;
    float* o1 = o0 + (size_t)8 * DM;
#pragma unroll
    for (int nf = 0; nf < 8; ++nf) {
        int d = nf * 8 + colb;
        *(float2*)(o0 + d) = make_float2(pvacc[nf][0] * iv0, pvacc[nf][1] * iv0);
        *(float2*)(o1 + d) = make_float2(pvacc[nf][2] * iv1, pvacc[nf][3] * iv1);
    }
}

// =========================== launch =======================================
extern "C" void kernel_launch(void* const* d_in, const int* in_sizes, int n_in,
                              void* d_out, int out_size)
{
    const float* inputs = (const float*)d_in[0];
    const float* mem    = (const float*)d_in[1];
    const float* r      = (const float*)d_in[2];
    const float* W_qkv  = (const float*)d_in[3];
    const float* b_qkv  = (const float*)d_in[4];
    const float* W_r    = (const float*)d_in[5];
    const float* b_r    = (const float*)d_in[6];
    const float* W_o    = (const float*)d_in[7];
    const float* b_o    = (const float*)d_in[8];
    const float* u      = (const float*)d_in[9];
    const float* v      = (const float*)d_in[10];
    float* out = (float*)d_out;

    float *pw, *prp, *pattn;
    __nv_bfloat16 *pah, *pal, *prh, *prl, *poh, *pol;
    __nv_bfloat16 *pwqh, *pwql, *pwrh, *pwrl, *pwoh, *pwol;
    cudaGetSymbolAddress((void**)&pw,    g_w);
    cudaGetSymbolAddress((void**)&prp,   g_rp);
    cudaGetSymbolAddress((void**)&pattn, g_attn);
    cudaGetSymbolAddress((void**)&pah,   g_ah);
    cudaGetSymbolAddress((void**)&pal,   g_al);
    cudaGetSymbolAddress((void**)&prh,   g_rh);
    cudaGetSymbolAddress((void**)&prl,   g_rl);
    cudaGetSymbolAddress((void**)&poh,   g_oh);
    cudaGetSymbolAddress((void**)&pol,   g_ol);
    cudaGetSymbolAddress((void**)&pwqh,  g_wqh);
    cudaGetSymbolAddress((void**)&pwql,  g_wql);
    cudaGetSymbolAddress((void**)&pwrh,  g_wrh);
    cudaGetSymbolAddress((void**)&pwrl,  g_wrl);
    cudaGetSymbolAddress((void**)&pwoh,  g_woh);
    cudaGetSymbolAddress((void**)&pwol,  g_wol);

    cudaFuncSetAttribute(gemm_bf3, cudaFuncAttributeMaxDynamicSharedMemorySize, GEMM_SMEM);
    cudaFuncSetAttribute(bd_mma, cudaFuncAttributeMaxDynamicSharedMemorySize, SCORE_SMEM);
    cudaFuncSetAttribute(attn_flash, cudaFuncAttributeMaxDynamicSharedMemorySize, ATTN_SMEM);

    dim3 blk(256);

    // --- dense GEMM input splits ---
    split_concat<<<4096, blk>>>(mem, inputs, pah, pal);
    split_plain<<<4096, blk>>>(r, prh, prl);
    split_transpose<<<dim3(3072 / 32, 1024 / 32), blk>>>(W_qkv, pwqh, pwql, 3072);
    split_transpose<<<dim3(1024 / 32, 1024 / 32), blk>>>(W_r,   pwrh, pwrl, 1024);
    split_transpose<<<dim3(1024 / 32, 1024 / 32), blk>>>(W_o,   pwoh, pwol, 1024);

    // 1) w = cat @ W_qkv + b_qkv (skip q cols for memory rows) ; 2) rp = r @ W_r
    gemm_bf3<<<dim3(3072 / 128, 4096 / 128), blk, GEMM_SMEM>>>(pah, pal, pwqh, pwql, b_qkv, pw, 3072, 1);
    gemm_bf3<<<dim3(1024 / 128, 4096 / 128), blk, GEMM_SMEM>>>(prh, prl, pwrh, pwrl, b_r, prp, 1024, 0);

    // --- per-head attention operand splits ---
    split_heads<<<4096, blk>>>(u, v);
    split_vt<<<dim3(KL / 64, BQ * NH), blk>>>();

    // 3) BD (pre-shifted) -> g_bd
    bd_mma<<<dim3(KL / 128, QL / 128, BQ * NH), blk, SCORE_SMEM>>>();

    // 4) fused AC + online softmax + P@V -> g_attn
    attn_flash<<<dim3(QL / 128, BQ * NH), blk, ATTN_SMEM>>>();

    // 5) final projection
    split_plain<<<2048, blk>>>(pattn, poh, pol);
    gemm_bf3<<<dim3(1024 / 128, 2048 / 128), blk, GEMM_SMEM>>>(poh, pol, pwoh, pwol, b_o, out, 1024, 0);
}

// round 8
// speedup vs baseline: 1.2333x; 1.0128x over previous
#include <cuda_runtime.h>
#include <cuda_bf16.h>
#include <cstdint>
#include <cstddef>

#define BQ 2
#define QL 1024
#define ML 1024
#define KL 2048
#define DM 1024
#define NH 16
#define DH 64

// ---------------- scratch (device globals: allocation-free) ----------------
__device__ float g_bd[(size_t)32 * 1024 * 2048];    // BD (pre-shifted) [B*H, Q, K]

// dense GEMM bf16 hi/lo splits (A-side activations, K-major weights)
__device__ __nv_bfloat16 g_ah[(size_t)4096 * 1024], g_al[(size_t)4096 * 1024];
__device__ __nv_bfloat16 g_rh[(size_t)4096 * 1024], g_rl[(size_t)4096 * 1024];
__device__ __nv_bfloat16 g_oh[(size_t)2048 * 1024], g_ol[(size_t)2048 * 1024];
__device__ __nv_bfloat16 g_wqh[(size_t)3072 * 1024], g_wql[(size_t)3072 * 1024];
__device__ __nv_bfloat16 g_wrh[(size_t)1024 * 1024], g_wrl[(size_t)1024 * 1024];
__device__ __nv_bfloat16 g_woh[(size_t)1024 * 1024], g_wol[(size_t)1024 * 1024];

// per-head attention operands (bf16 hi/lo), written by GEMM epilogues
__device__ __nv_bfloat16 g_quh[(size_t)32 * 1024 * 64], g_qul[(size_t)32 * 1024 * 64];
__device__ __nv_bfloat16 g_qvh[(size_t)32 * 1024 * 64], g_qvl[(size_t)32 * 1024 * 64];
__device__ __nv_bfloat16 g_khh[(size_t)32 * 2048 * 64], g_khl[(size_t)32 * 2048 * 64];
__device__ __nv_bfloat16 g_rrh[(size_t)32 * 2048 * 64], g_rrl[(size_t)32 * 2048 * 64];
__device__ __nv_bfloat16 g_vjh[(size_t)32 * 2048 * 64], g_vjl[(size_t)32 * 2048 * 64]; // [bh][j][d]

// ======================= helpers ===========================================
__device__ __forceinline__ uint32_t smem_u32(const void* p) {
    uint32_t a;
    asm("{ .reg .u64 t; cvta.to.shared.u64 t, %1; cvt.u32.u64 %0, t; }"
        : "=r"(a) : "l"(p));
    return a;
}
__device__ __forceinline__ void split1(float x, __nv_bfloat16& h, __nv_bfloat16& l) {
    h = __float2bfloat16_rn(x);
    l = __float2bfloat16_rn(x - __bfloat162float(h));
}
__device__ __forceinline__ uint32_t pack2(__nv_bfloat16 a, __nv_bfloat16 b) {
    __nv_bfloat162 v = make_bfloat162(a, b);
    return *(uint32_t*)&v;
}
__device__ __forceinline__ void ldmx4(uint32_t a[4], uint32_t addr) {
    asm volatile("ldmatrix.sync.aligned.m8n8.x4.shared.b16 {%0,%1,%2,%3}, [%4];"
        : "=r"(a[0]), "=r"(a[1]), "=r"(a[2]), "=r"(a[3]) : "r"(addr));
}
__device__ __forceinline__ void ldmx2(uint32_t a[2], uint32_t addr) {
    asm volatile("ldmatrix.sync.aligned.m8n8.x2.shared.b16 {%0,%1}, [%2];"
        : "=r"(a[0]), "=r"(a[1]) : "r"(addr));
}
__device__ __forceinline__ void ldmx2t(uint32_t a[2], uint32_t addr) {
    asm volatile("ldmatrix.sync.aligned.m8n8.x2.trans.shared.b16 {%0,%1}, [%2];"
        : "=r"(a[0]), "=r"(a[1]) : "r"(addr));
}
__device__ __forceinline__ void mma16816(float c[4], const uint32_t a[4], const uint32_t b[2]) {
    asm volatile("mma.sync.aligned.m16n8k16.row.col.f32.bf16.bf16.f32 "
        "{%0,%1,%2,%3}, {%4,%5,%6,%7}, {%8,%9}, {%0,%1,%2,%3};"
        : "+f"(c[0]), "+f"(c[1]), "+f"(c[2]), "+f"(c[3])
        : "r"(a[0]), "r"(a[1]), "r"(a[2]), "r"(a[3]), "r"(b[0]), "r"(b[1]));
}
#define CP16(dst, src) \
    asm volatile("cp.async.cg.shared.global [%0], [%1], 16;" :: "r"(dst), "l"(src) : "memory")
#define CP_COMMIT() asm volatile("cp.async.commit_group;" ::: "memory")
#define CP_WAIT(n)  asm volatile("cp.async.wait_group %0;" :: "n"(n) : "memory")

// ===================== prep: split kernels ==================================
__global__ __launch_bounds__(256)
void split_concat(const float* __restrict__ mem, const float* __restrict__ inp,
                  __nv_bfloat16* __restrict__ hi, __nv_bfloat16* __restrict__ lo)
{
    size_t idx = ((size_t)blockIdx.x * 256 + threadIdx.x) * 4;
    size_t row = idx >> 10;
    int col = (int)(idx & 1023);
    int b = (int)(row >> 11);
    int k = (int)(row & 2047);
    const float* src = (k < ML) ? mem + ((size_t)(b * ML + k) << 10)
                                : inp + ((size_t)(b * QL + (k - ML)) << 10);
    float4 v = *(const float4*)(src + col);
    __nv_bfloat16 h0, h1, h2, h3, l0, l1, l2, l3;
    split1(v.x, h0, l0); split1(v.y, h1, l1);
    split1(v.z, h2, l2); split1(v.w, h3, l3);
    __nv_bfloat162* H = (__nv_bfloat162*)(hi + idx);
    __nv_bfloat162* L = (__nv_bfloat162*)(lo + idx);
    H[0] = make_bfloat162(h0, h1); H[1] = make_bfloat162(h2, h3);
    L[0] = make_bfloat162(l0, l1); L[1] = make_bfloat162(l2, l3);
}

__global__ __launch_bounds__(256)
void split_plain(const float* __restrict__ src,
                 __nv_bfloat16* __restrict__ hi, __nv_bfloat16* __restrict__ lo)
{
    size_t idx = ((size_t)blockIdx.x * 256 + threadIdx.x) * 4;
    float4 v = *(const float4*)(src + idx);
    __nv_bfloat16 h0, h1, h2, h3, l0, l1, l2, l3;
    split1(v.x, h0, l0); split1(v.y, h1, l1);
    split1(v.z, h2, l2); split1(v.w, h3, l3);
    __nv_bfloat162* H = (__nv_bfloat162*)(hi + idx);
    __nv_bfloat162* L = (__nv_bfloat162*)(lo + idx);
    H[0] = make_bfloat162(h0, h1); H[1] = make_bfloat162(h2, h3);
    L[0] = make_bfloat162(l0, l1); L[1] = make_bfloat162(l2, l3);
}

__global__ __launch_bounds__(256)
void split_transpose(const float* __restrict__ in,
                     __nv_bfloat16* __restrict__ hi, __nv_bfloat16* __restrict__ lo, int N)
{
    __shared__ float s[32][33];
    const int nx = blockIdx.x * 32;
    const int ky = blockIdx.y * 32;
    const int tx = threadIdx.x & 31;
    const int ty = threadIdx.x >> 5;
#pragma unroll
    for (int r = 0; r < 32; r += 8)
        s[ty + r][tx] = in[(size_t)(ky + ty + r) * N + nx + tx];
    __syncthreads();
#pragma unroll
    for (int r = 0; r < 32; r += 8) {
        float x = s[tx][ty + r];
        __nv_bfloat16 h, l;
        split1(x, h, l);
        size_t o = (size_t)(nx + ty + r) * DM + ky + tx;
        hi[o] = h;
        lo[o] = l;
    }
}

// ============== dense GEMM: mma.sync bf16 3-term split ======================
// MODE 0: fp32 C = A@W + bias.  MODE 1: qkv fused epilogue -> per-head operands.
// MODE 2: r-proj fused epilogue -> rr hi/lo.
#define RS 80
#define ARRB (128 * RS)
#define STGB (4 * ARRB)
#define NSTG 4
#define GEMM_SMEM (NSTG * STGB)

template<int MODE>
__device__ __forceinline__ void store_opnd(int m, int n, float x0, float x1,
                                           const float* __restrict__ u,
                                           const float* __restrict__ v)
{
    int b = m >> 11, tok = m & 2047;
    __nv_bfloat16 h0, l0, h1, l1;
    if (MODE == 2) {
        int h = n >> 6, d = n & 63;
        size_t o = ((size_t)(b * NH + h) * KL + tok) * DH + d;
        split1(x0, h0, l0); split1(x1, h1, l1);
        *(uint32_t*)(g_rrh + o) = pack2(h0, h1);
        *(uint32_t*)(g_rrl + o) = pack2(l0, l1);
    } else if (n < 1024) {          // q columns (only non-mem rows reach here)
        int h = n >> 6, d = n & 63, i = tok - ML;
        size_t o = ((size_t)(b * NH + h) * QL + i) * DH + d;
        split1(x0 + u[n], h0, l0); split1(x1 + u[n + 1], h1, l1);
        *(uint32_t*)(g_quh + o) = pack2(h0, h1);
        *(uint32_t*)(g_qul + o) = pack2(l0, l1);
        split1(x0 + v[n], h0, l0); split1(x1 + v[n + 1], h1, l1);
        *(uint32_t*)(g_qvh + o) = pack2(h0, h1);
        *(uint32_t*)(g_qvl + o) = pack2(l0, l1);
    } else if (n < 2048) {          // v columns -> [j][d]
        int h = (n - 1024) >> 6, d = n & 63;
        size_t o = ((size_t)(b * NH + h) * KL + tok) * DH + d;
        split1(x0, h0, l0); split1(x1, h1, l1);
        *(uint32_t*)(g_vjh + o) = pack2(h0, h1);
        *(uint32_t*)(g_vjl + o) = pack2(l0, l1);
    } else {                        // k columns
        int h = (n - 2048) >> 6, d = n & 63;
        size_t o = ((size_t)(b * NH + h) * KL + tok) * DH + d;
        split1(x0, h0, l0); split1(x1, h1, l1);
        *(uint32_t*)(g_khh + o) = pack2(h0, h1);
        *(uint32_t*)(g_khl + o) = pack2(l0, l1);
    }
}

template<int MODE>
__global__ __launch_bounds__(256, 1)
void gemm_bf3(const __nv_bfloat16* __restrict__ Ah, const __nv_bfloat16* __restrict__ Al,
              const __nv_bfloat16* __restrict__ Bh, const __nv_bfloat16* __restrict__ Bl,
              const float* __restrict__ bias, float* __restrict__ C, int N,
              const float* __restrict__ u, const float* __restrict__ v)
{
    extern __shared__ char sm[];
    const uint32_t sb = smem_u32(sm);
    const int t = threadIdx.x;
    const int lane = t & 31;
    const int wid = t >> 5;
    const int m0 = blockIdx.y * 128;
    const int n0 = blockIdx.x * 128;
    // qkv: q columns unused for memory rows
    if (MODE == 1 && n0 < 1024 && ((m0 & 2047) + 128) <= ML) return;

    const int warp_m = (wid & 1) * 64;
    const int warp_n = (wid >> 1) * 32;

    const __nv_bfloat16* srcs[4] = {
        Ah + (size_t)m0 * DM, Al + (size_t)m0 * DM,
        Bh + (size_t)n0 * DM, Bl + (size_t)n0 * DM
    };

    auto issue_stage = [&](int c) {
        uint32_t dst0 = sb + (uint32_t)(c & 3) * STGB;
#pragma unroll
        for (int arr = 0; arr < 4; ++arr) {
#pragma unroll
            for (int rep = 0; rep < 2; ++rep) {
                int ci = t + rep * 256;
                int row = ci >> 2;
                int kc = ci & 3;
                uint32_t dst = dst0 + arr * ARRB + row * RS + kc * 16;
                const __nv_bfloat16* src = srcs[arr] + (size_t)row * DM + c * 32 + kc * 8;
                CP16(dst, src);
            }
        }
    };

    float acc[4][4][4];
#pragma unroll
    for (int im = 0; im < 4; ++im)
#pragma unroll
        for (int jn = 0; jn < 4; ++jn)
#pragma unroll
            for (int q = 0; q < 4; ++q) acc[im][jn][q] = 0.f;

#pragma unroll
    for (int s = 0; s < NSTG - 1; ++s) { issue_stage(s); CP_COMMIT(); }

    const int NCH = DM / 32;
    for (int c = 0; c < NCH; ++c) {
        CP_WAIT(2);
        __syncthreads();
        if (c + 3 < NCH) issue_stage(c + 3);
        CP_COMMIT();

        const uint32_t st = sb + (uint32_t)(c & 3) * STGB;
        const int mrow = lane & 15;
        const int khalf = lane >> 4;
        const int nrow = lane & 7;
        const int khalfb = (lane >> 3) & 1;
#pragma unroll
        for (int kk = 0; kk < 32; kk += 16) {
            uint32_t ah[4][4], al[4][4], bh[4][2], bl[4][2];
#pragma unroll
            for (int im = 0; im < 4; ++im) {
                uint32_t aaddr = st + (warp_m + im * 16 + mrow) * RS + (kk + khalf * 8) * 2;
                ldmx4(ah[im], aaddr);
                ldmx4(al[im], aaddr + ARRB);
            }
#pragma unroll
            for (int jn = 0; jn < 4; ++jn) {
                uint32_t baddr = st + 2 * ARRB + (warp_n + jn * 8 + nrow) * RS + (kk + khalfb * 8) * 2;
                ldmx2(bh[jn], baddr);
                ldmx2(bl[jn], baddr + ARRB);
            }
#pragma unroll
            for (int im = 0; im < 4; ++im)
#pragma unroll
                for (int jn = 0; jn < 4; ++jn) {
                    mma16816(acc[im][jn], ah[im], bh[jn]);
                    mma16816(acc[im][jn], ah[im], bl[jn]);
                    mma16816(acc[im][jn], al[im], bh[jn]);
                }
        }
    }

    if (MODE == 0) {
#pragma unroll
        for (int im = 0; im < 4; ++im) {
            int m = m0 + warp_m + im * 16 + (lane >> 2);
#pragma unroll
            for (int jn = 0; jn < 4; ++jn) {
                int n = n0 + warp_n + jn * 8 + (lane & 3) * 2;
                float b0 = bias[n], b1 = bias[n + 1];
                float2 v0, v1;
                v0.x = acc[im][jn][0] + b0; v0.y = acc[im][jn][1] + b1;
                v1.x = acc[im][jn][2] + b0; v1.y = acc[im][jn][3] + b1;
                *(float2*)(C + (size_t)m * N + n) = v0;
                *(float2*)(C + (size_t)(m + 8) * N + n) = v1;
            }
        }
    } else {
#pragma unroll
        for (int im = 0; im < 4; ++im) {
            int m = m0 + warp_m + im * 16 + (lane >> 2);
#pragma unroll
            for (int jn = 0; jn < 4; ++jn) {
                int n = n0 + warp_n + jn * 8 + (lane & 3) * 2;
                float b0 = bias[n], b1 = bias[n + 1];
                store_opnd<MODE>(m, n, acc[im][jn][0] + b0, acc[im][jn][1] + b1, u, v);
                store_opnd<MODE>(m + 8, n, acc[im][jn][2] + b0, acc[im][jn][3] + b1, u, v);
            }
        }
    }
}

// ============== BD score GEMM (mma, K=64, pre-shifted scatter) ==============
#define SRS 144
#define SARRB (128 * SRS)
#define SCORE_SMEM (4 * SARRB)

__global__ __launch_bounds__(256, 1)
void bd_mma()
{
    const int bh = blockIdx.z;
    const int i0 = blockIdx.y * 128;
    const int p0 = blockIdx.x * 128;
    if (i0 + p0 + 254 < QL - 1) return;

    extern __shared__ char sm[];
    const uint32_t sb = smem_u32(sm);
    const int t = threadIdx.x;
    const int lane = t & 31;
    const int wid = t >> 5;
    const int warp_m = (wid & 1) * 64;
    const int warp_n = (wid >> 1) * 32;

    const __nv_bfloat16* srcs[4] = {
        g_qvh + ((size_t)bh * QL + i0) * DH,
        g_qvl + ((size_t)bh * QL + i0) * DH,
        g_rrh + ((size_t)bh * KL + p0) * DH,
        g_rrl + ((size_t)bh * KL + p0) * DH
    };
#pragma unroll
    for (int arr = 0; arr < 4; ++arr) {
#pragma unroll
        for (int rep = 0; rep < 4; ++rep) {
            int ci = t + rep * 256;
            int row = ci >> 3;
            int kc = ci & 7;
            uint32_t dst = sb + arr * SARRB + row * SRS + kc * 16;
            CP16(dst, srcs[arr] + (size_t)row * DH + kc * 8);
        }
    }
    CP_COMMIT();
    CP_WAIT(0);
    __syncthreads();

    float acc[4][4][4];
#pragma unroll
    for (int im = 0; im < 4; ++im)
#pragma unroll
        for (int jn = 0; jn < 4; ++jn)
#pragma unroll
            for (int q = 0; q < 4; ++q) acc[im][jn][q] = 0.f;

    const int mrow = lane & 15;
    const int khalf = lane >> 4;
    const int nrow = lane & 7;
    const int khalfb = (lane >> 3) & 1;
#pragma unroll
    for (int kk = 0; kk < 64; kk += 16) {
        uint32_t ah[4][4], al[4][4], bh[4][2], bl[4][2];
#pragma unroll
        for (int im = 0; im < 4; ++im) {
            uint32_t aaddr = sb + (warp_m + im * 16 + mrow) * SRS + (kk + khalf * 8) * 2;
            ldmx4(ah[im], aaddr);
            ldmx4(al[im], aaddr + SARRB);
        }
#pragma unroll
        for (int jn = 0; jn < 4; ++jn) {
            uint32_t baddr = sb + 2 * SARRB + (warp_n + jn * 8 + nrow) * SRS + (kk + khalfb * 8) * 2;
            ldmx2(bh[jn], baddr);
            ldmx2(bl[jn], baddr + SARRB);
        }
#pragma unroll
        for (int im = 0; im < 4; ++im)
#pragma unroll
            for (int jn = 0; jn < 4; ++jn) {
                mma16816(acc[im][jn], ah[im], bh[jn]);
                mma16816(acc[im][jn], ah[im], bl[jn]);
                mma16816(acc[im][jn], al[im], bh[jn]);
            }
    }

#pragma unroll
    for (int im = 0; im < 4; ++im) {
        int m = i0 + warp_m + im * 16 + (lane >> 2);
        float* r0 = g_bd + ((size_t)bh * QL + m) * KL;
        float* r1 = g_bd + ((size_t)bh * QL + m + 8) * KL;
        int sh0 = m - (QL - 1);
        int sh1 = m + 8 - (QL - 1);
#pragma unroll
        for (int jn = 0; jn < 4; ++jn) {
            int p = p0 + warp_n + jn * 8 + (lane & 3) * 2;
            int j0a = p + sh0;
            int j1a = p + sh1;
            if (j0a >= 0)     r0[j0a]     = acc[im][jn][0];
            if (j0a + 1 >= 0) r0[j0a + 1] = acc[im][jn][1];
            if (j1a >= 0)     r1[j1a]     = acc[im][jn][2];
            if (j1a + 1 >= 0) r1[j1a + 1] = acc[im][jn][3];
        }
    }
}

// ========== warp-autonomous flash attention: AC in-register + PV ===========
// smem: Q hi/lo (36864) | K dbl (2x36864) | V[j][d] dbl (2x36864)
#define FCH 128
#define AQ_OFF 0u
#define AK_OFF 36864u
#define AV_OFF 110592u
#define ABUF 36864u
#define ATTN_SMEM 184320

__global__ __launch_bounds__(256, 1)
void attn_flash()
{
    extern __shared__ char sm[];
    const uint32_t sb = smem_u32(sm);
    const int bh = blockIdx.y;
    const int b = bh >> 4, h = bh & 15;
    const int i0 = (gridDim.x - 1 - blockIdx.x) * 128;   // big-work tiles first
    const int t = threadIdx.x, lane = t & 31, wid = t >> 5;
    const int warp_m = wid * 16;

    const __nv_bfloat16* Kh  = g_khh + (size_t)bh * KL * DH;
    const __nv_bfloat16* Klo = g_khl + (size_t)bh * KL * DH;
    const __nv_bfloat16* Vjh = g_vjh + (size_t)bh * KL * DH;
    const __nv_bfloat16* Vjl = g_vjl + (size_t)bh * KL * DH;

    // Q tile load (hi/lo)
    {
        const __nv_bfloat16* Qh = g_quh + ((size_t)bh * QL + i0) * DH;
        const __nv_bfloat16* Ql = g_qul + ((size_t)bh * QL + i0) * DH;
#pragma unroll
        for (int rep = 0; rep < 4; ++rep) {
            int ci = t + rep * 256;
            int row = ci >> 3, kc = ci & 7;
            uint32_t dst = sb + AQ_OFF + row * SRS + kc * 16;
            CP16(dst, Qh + (size_t)row * DH + kc * 8);
            CP16(dst + 18432u, Ql + (size_t)row * DH + kc * 8);
        }
    }
    CP_COMMIT();

    auto loadKV = [&](int c) {
        uint32_t kd = sb + AK_OFF + (uint32_t)(c & 1) * ABUF;
        uint32_t vd = sb + AV_OFF + (uint32_t)(c & 1) * ABUF;
#pragma unroll
        for (int rep = 0; rep < 4; ++rep) {
            int ci = t + rep * 256;
            int row = ci >> 3, kc = ci & 7;
            uint32_t o = row * SRS + kc * 16;
            CP16(kd + o, Kh + (size_t)(c * FCH + row) * DH + kc * 8);
            CP16(kd + o + 18432u, Klo + (size_t)(c * FCH + row) * DH + kc * 8);
            CP16(vd + o, Vjh + (size_t)(c * FCH + row) * DH + kc * 8);
            CP16(vd + o + 18432u, Vjl + (size_t)(c * FCH + row) * DH + kc * 8);
        }
    };

    const int nch = (ML + i0 + 128) / FCH;   // >= 9 always
    loadKV(0); CP_COMMIT();
    loadKV(1); CP_COMMIT();

    // Q A-fragments cached in registers
    const int mrow = lane & 15, khalf = lane >> 4;
    const int nrow = lane & 7, khalfb = (lane >> 3) & 1;
    const int lane16 = lane & 15;
    uint32_t aqh[4][4], aql[4][4];
    CP_WAIT(2);
    __syncthreads();
#pragma unroll
    for (int kf = 0; kf < 4; ++kf) {
        uint32_t aaddr = sb + AQ_OFF + (warp_m + mrow) * SRS + (kf * 16 + khalf * 8) * 2;
        ldmx4(aqh[kf], aaddr);
        ldmx4(aql[kf], aaddr + 18432u);
    }

    const int r0 = lane >> 2;
    const int colb = (lane & 3) * 2;
    const float* bdr0 = g_bd + ((size_t)bh * QL + i0 + warp_m + r0) * KL;
    const float* bdr1 = bdr0 + (size_t)8 * KL;
    const int lim0 = ML + i0 + warp_m + r0;
    const int lim1 = lim0 + 8;

    float pvacc[8][4];
#pragma unroll
    for (int nf = 0; nf < 8; ++nf)
#pragma unroll
        for (int q = 0; q < 4; ++q) pvacc[nf][q] = 0.f;
    float ssum0 = 0.f, ssum1 = 0.f;
    float mold0 = -1e30f, mold1 = -1e30f;

    for (int c = 0; c < nch; ++c) {
        CP_WAIT(1);
        __syncthreads();
        const uint32_t kst = sb + AK_OFF + (uint32_t)(c & 1) * ABUF;
        const uint32_t vst = sb + AV_OFF + (uint32_t)(c & 1) * ABUF;
        const int j0 = c * FCH;

        // ---- S = (q+u) . K^T ----
        float S[16][4];
#pragma unroll
        for (int nf = 0; nf < 16; ++nf) {
            S[nf][0] = S[nf][1] = S[nf][2] = S[nf][3] = 0.f;
#pragma unroll
            for (int kf = 0; kf < 4; ++kf) {
                uint32_t bhh[2], bll[2];
                uint32_t baddr = kst + (nf * 8 + nrow) * SRS + (kf * 16 + khalfb * 8) * 2;
                ldmx2(bhh, baddr);
                ldmx2(bll, baddr + 18432u);
                mma16816(S[nf], aqh[kf], bhh);
                mma16816(S[nf], aqh[kf], bll);
                mma16816(S[nf], aql[kf], bhh);
            }
        }

        // ---- + BD, scale, mask, row max ----
        const bool nomask = (j0 + 127) <= lim0;
        float mx0 = -1e30f, mx1 = -1e30f;
#pragma unroll
        for (int nf = 0; nf < 16; ++nf) {
            int jc = j0 + nf * 8 + colb;
            float2 b0 = *(const float2*)(bdr0 + jc);
            float2 b1 = *(const float2*)(bdr1 + jc);
            float s0 = (S[nf][0] + b0.x) * 0.125f;
            float s1 = (S[nf][1] + b0.y) * 0.125f;
            float s2 = (S[nf][2] + b1.x) * 0.125f;
            float s3 = (S[nf][3] + b1.y) * 0.125f;
            if (!nomask) {
                s0 = (jc     <= lim0) ? s0 : -1e30f;
                s1 = (jc + 1 <= lim0) ? s1 : -1e30f;
                s2 = (jc     <= lim1) ? s2 : -1e30f;
                s3 = (jc + 1 <= lim1) ? s3 : -1e30f;
            }
            S[nf][0] = s0; S[nf][1] = s1; S[nf][2] = s2; S[nf][3] = s3;
            mx0 = fmaxf(mx0, fmaxf(s0, s1));
            mx1 = fmaxf(mx1, fmaxf(s2, s3));
        }
        mx0 = fmaxf(mx0, __shfl_xor_sync(0xffffffffu, mx0, 1));
        mx0 = fmaxf(mx0, __shfl_xor_sync(0xffffffffu, mx0, 2));
        mx1 = fmaxf(mx1, __shfl_xor_sync(0xffffffffu, mx1, 1));
        mx1 = fmaxf(mx1, __shfl_xor_sync(0xffffffffu, mx1, 2));
        const float mnew0 = fmaxf(mold0, mx0);
        const float mnew1 = fmaxf(mold1, mx1);
        const float sc0 = __expf(mold0 - mnew0);
        const float sc1 = __expf(mold1 - mnew1);
        mold0 = mnew0; mold1 = mnew1;
        ssum0 *= sc0; ssum1 *= sc1;
#pragma unroll
        for (int nf = 0; nf < 8; ++nf) {
            pvacc[nf][0] *= sc0; pvacc[nf][1] *= sc0;
            pvacc[nf][2] *= sc1; pvacc[nf][3] *= sc1;
        }
#pragma unroll
        for (int nf = 0; nf < 16; ++nf) {
            S[nf][0] = __expf(S[nf][0] - mnew0);
            S[nf][1] = __expf(S[nf][1] - mnew0);
            S[nf][2] = __expf(S[nf][2] - mnew1);
            S[nf][3] = __expf(S[nf][3] - mnew1);
            ssum0 += S[nf][0] + S[nf][1];
            ssum1 += S[nf][2] + S[nf][3];
        }

        // ---- P (bf16 hi/lo from fragments) @ V (ldmatrix.trans of [j][d]) ----
#pragma unroll
        for (int kf = 0; kf < 8; ++kf) {
            uint32_t pah[4], pal[4];
            __nv_bfloat16 h0, l0, h1, l1;
            split1(S[2 * kf][0], h0, l0);     split1(S[2 * kf][1], h1, l1);
            pah[0] = pack2(h0, h1);           pal[0] = pack2(l0, l1);
            split1(S[2 * kf][2], h0, l0);     split1(S[2 * kf][3], h1, l1);
            pah[1] = pack2(h0, h1);           pal[1] = pack2(l0, l1);
            split1(S[2 * kf + 1][0], h0, l0); split1(S[2 * kf + 1][1], h1, l1);
            pah[2] = pack2(h0, h1);           pal[2] = pack2(l0, l1);
            split1(S[2 * kf + 1][2], h0, l0); split1(S[2 * kf + 1][3], h1, l1);
            pah[3] = pack2(h0, h1);           pal[3] = pack2(l0, l1);
#pragma unroll
            for (int nf = 0; nf < 8; ++nf) {
                uint32_t bhh[2], bll[2];
                uint32_t baddr = vst + (kf * 16 + lane16) * SRS + nf * 16;
                ldmx2t(bhh, baddr);
                ldmx2t(bll, baddr + 18432u);
                mma16816(pvacc[nf], pah, bhh);
                mma16816(pvacc[nf], pah, bll);
                mma16816(pvacc[nf], pal, bhh);
            }
        }

        __syncthreads();
        if (c + 2 < nch) loadKV(c + 2);
        CP_COMMIT();
    }

    // ---- epilogue: normalize, split to bf16 hi/lo, store to g_oh/g_ol ----
    ssum0 += __shfl_xor_sync(0xffffffffu, ssum0, 1);
    ssum0 += __shfl_xor_sync(0xffffffffu, ssum0, 2);
    ssum1 += __shfl_xor_sync(0xffffffffu, ssum1, 1);
    ssum1 += __shfl_xor_sync(0xffffffffu, ssum1, 2);
    const float iv0 = 1.f / ssum0;
    const float iv1 = 1.f / ssum1;
    const size_t orow0 = (size_t)(b * QL + i0 + warp_m + r0) * DM + h * DH;
    const size_t orow1 = orow0 + (size_t)8 * DM;
#pragma unroll
    for (int nf = 0; nf < 8; ++nf) {
        int d = nf * 8 + colb;
        __nv_bfloat16 hh0, ll0, hh1, ll1;
        split1(pvacc[nf][0] * iv0, hh0, ll0);
        split1(pvacc[nf][1] * iv0, hh1, ll1);
        *(uint32_t*)(g_oh + orow0 + d) = pack2(hh0, hh1);
        *(uint32_t*)(g_ol + orow0 + d) = pack2(ll0, ll1);
        split1(pvacc[nf][2] * iv1, hh0, ll0);
        split1(pvacc[nf][3] * iv1, hh1, ll1);
        *(uint32_t*)(g_oh + orow1 + d) = pack2(hh0, hh1);
        *(uint32_t*)(g_ol + orow1 + d) = pack2(ll0, ll1);
    }
}

// =========================== launch =======================================
extern "C" void kernel_launch(void* const* d_in, const int* in_sizes, int n_in,
                              void* d_out, int out_size)
{
    const float* inputs = (const float*)d_in[0];
    const float* mem    = (const float*)d_in[1];
    const float* r      = (const float*)d_in[2];
    const float* W_qkv  = (const float*)d_in[3];
    const float* b_qkv  = (const float*)d_in[4];
    const float* W_r    = (const float*)d_in[5];
    const float* b_r    = (const float*)d_in[6];
    const float* W_o    = (const float*)d_in[7];
    const float* b_o    = (const float*)d_in[8];
    const float* u      = (const float*)d_in[9];
    const float* v      = (const float*)d_in[10];
    float* out = (float*)d_out;

    __nv_bfloat16 *pah, *pal, *prh, *prl, *poh, *pol;
    __nv_bfloat16 *pwqh, *pwql, *pwrh, *pwrl, *pwoh, *pwol;
    cudaGetSymbolAddress((void**)&pah,   g_ah);
    cudaGetSymbolAddress((void**)&pal,   g_al);
    cudaGetSymbolAddress((void**)&prh,   g_rh);
    cudaGetSymbolAddress((void**)&prl,   g_rl);
    cudaGetSymbolAddress((void**)&poh,   g_oh);
    cudaGetSymbolAddress((void**)&pol,   g_ol);
    cudaGetSymbolAddress((void**)&pwqh,  g_wqh);
    cudaGetSymbolAddress((void**)&pwql,  g_wql);
    cudaGetSymbolAddress((void**)&pwrh,  g_wrh);
    cudaGetSymbolAddress((void**)&pwrl,  g_wrl);
    cudaGetSymbolAddress((void**)&pwoh,  g_woh);
    cudaGetSymbolAddress((void**)&pwol,  g_wol);

    cudaFuncSetAttribute(gemm_bf3<0>, cudaFuncAttributeMaxDynamicSharedMemorySize, GEMM_SMEM);
    cudaFuncSetAttribute(gemm_bf3<1>, cudaFuncAttributeMaxDynamicSharedMemorySize, GEMM_SMEM);
    cudaFuncSetAttribute(gemm_bf3<2>, cudaFuncAttributeMaxDynamicSharedMemorySize, GEMM_SMEM);
    cudaFuncSetAttribute(bd_mma, cudaFuncAttributeMaxDynamicSharedMemorySize, SCORE_SMEM);
    cudaFuncSetAttribute(attn_flash, cudaFuncAttributeMaxDynamicSharedMemorySize, ATTN_SMEM);

    dim3 blk(256);

    // --- A-side / weight splits ---
    split_concat<<<4096, blk>>>(mem, inputs, pah, pal);
    split_plain<<<4096, blk>>>(r, prh, prl);
    split_transpose<<<dim3(3072 / 32, 1024 / 32), blk>>>(W_qkv, pwqh, pwql, 3072);
    split_transpose<<<dim3(1024 / 32, 1024 / 32), blk>>>(W_r,   pwrh, pwrl, 1024);
    split_transpose<<<dim3(1024 / 32, 1024 / 32), blk>>>(W_o,   pwoh, pwol, 1024);

    // 1) qkv projection with fused per-head operand epilogue
    gemm_bf3<1><<<dim3(3072 / 128, 4096 / 128), blk, GEMM_SMEM>>>(
        pah, pal, pwqh, pwql, b_qkv, nullptr, 3072, u, v);
    // 2) r projection with fused rr epilogue
    gemm_bf3<2><<<dim3(1024 / 128, 4096 / 128), blk, GEMM_SMEM>>>(
        prh, prl, pwrh, pwrl, b_r, nullptr, 1024, nullptr, nullptr);

    // 3) BD (pre-shifted) -> g_bd
    bd_mma<<<dim3(KL / 128, QL / 128, BQ * NH), blk, SCORE_SMEM>>>();

    // 4) fused AC + online softmax + P@V -> g_oh/g_ol (bf16 hi/lo)
    attn_flash<<<dim3(QL / 128, BQ * NH), blk, ATTN_SMEM>>>();

    // 5) final projection -> d_out
    gemm_bf3<0><<<dim3(1024 / 128, 2048 / 128), blk, GEMM_SMEM>>>(
        poh, pol, pwoh, pwol, b_o, out, 1024, nullptr, nullptr);
}